// round 1
// baseline (speedup 1.0000x reference)
#include <cuda_runtime.h>
#include <math.h>

#define B_ 2
#define T_ 2048
#define C_ 2048
#define NK_ 16
#define NV_ 32
#define DK_ 128
#define DV_ 128
#define KEY_DIM_ 2048
#define VAL_DIM_ 4096
#define CONV_DIM_ 8192
#define BT_ (B_*T_)
#define LCH 64
#define NCH (T_/LCH)
#define SPLITV 2
#define DVS (DV_/SPLITV)

// ---------------- scratch (static device globals; no allocation) ----------------
__device__ float g_qkv [BT_*CONV_DIM_];
__device__ float g_z   [BT_*VAL_DIM_];
__device__ float g_q   [BT_*KEY_DIM_];
__device__ float g_k   [BT_*KEY_DIM_];
__device__ float g_v   [BT_*VAL_DIM_];
__device__ float g_braw[BT_*NV_];
__device__ float g_araw[BT_*NV_];
__device__ float g_beta[BT_*NV_];
__device__ float g_gg  [BT_*NV_];
__device__ float g_o   [BT_*VAL_DIM_];

// ---------------- SGEMM: C[M,N] = A[M,K] * B[N,K]^T  (both row-major) ----------------
__global__ void sgemm_nt(const float* __restrict__ A, const float* __restrict__ Bm,
                         float* __restrict__ C, int M, int N, int Kd)
{
    __shared__ float As[16][128];
    __shared__ float Bs[16][128];
    int tid = threadIdx.x;              // 256 threads
    int tx = tid & 15, ty = tid >> 4;
    int row0 = blockIdx.y * 128, col0 = blockIdx.x * 128;

    float acc[8][8];
#pragma unroll
    for (int m = 0; m < 8; m++)
#pragma unroll
        for (int n = 0; n < 8; n++) acc[m][n] = 0.f;

    for (int kt = 0; kt < Kd; kt += 16) {
#pragma unroll
        for (int i = 0; i < 2; i++) {
            int f = tid + i * 256;
            int r = f >> 2, c4 = (f & 3) << 2;
            int gr = row0 + r;
            float4 av = make_float4(0.f, 0.f, 0.f, 0.f);
            if (gr < M) av = *(const float4*)(A + (long)gr * Kd + kt + c4);
            As[c4][r] = av.x; As[c4+1][r] = av.y; As[c4+2][r] = av.z; As[c4+3][r] = av.w;
            int gn = col0 + r;
            float4 bv = make_float4(0.f, 0.f, 0.f, 0.f);
            if (gn < N) bv = *(const float4*)(Bm + (long)gn * Kd + kt + c4);
            Bs[c4][r] = bv.x; Bs[c4+1][r] = bv.y; Bs[c4+2][r] = bv.z; Bs[c4+3][r] = bv.w;
        }
        __syncthreads();
#pragma unroll
        for (int k = 0; k < 16; k++) {
            float ra[8], rb[8];
            *(float4*)&ra[0] = *(float4*)&As[k][ty * 8];
            *(float4*)&ra[4] = *(float4*)&As[k][ty * 8 + 4];
            *(float4*)&rb[0] = *(float4*)&Bs[k][tx * 8];
            *(float4*)&rb[4] = *(float4*)&Bs[k][tx * 8 + 4];
#pragma unroll
            for (int m = 0; m < 8; m++)
#pragma unroll
                for (int n = 0; n < 8; n++) acc[m][n] += ra[m] * rb[n];
        }
        __syncthreads();
    }
#pragma unroll
    for (int m = 0; m < 8; m++) {
        int gr = row0 + ty * 8 + m;
        if (gr >= M) continue;
#pragma unroll
        for (int n4 = 0; n4 < 8; n4 += 4) {
            int gc = col0 + tx * 8 + n4;
            if (gc < N) {
                float4 w = make_float4(acc[m][n4], acc[m][n4+1], acc[m][n4+2], acc[m][n4+3]);
                *(float4*)(C + (long)gr * N + gc) = w;
            }
        }
    }
}

// ---------------- beta / g finalize ----------------
__global__ void betag_kernel(const float* __restrict__ dt_bias, const float* __restrict__ A_log)
{
    int i = blockIdx.x * blockDim.x + threadIdx.x;
    if (i >= BT_ * NV_) return;
    int h = i & (NV_ - 1);
    g_beta[i] = 1.f / (1.f + expf(-g_braw[i]));
    float a = g_araw[i] + dt_bias[h];
    float sp = (a > 20.f) ? a : log1pf(expf(a));
    g_gg[i] = -expf(A_log[h]) * sp;
}

// ---------------- causal depthwise conv(K=4) + silu + q/k L2 norm ----------------
__global__ void conv_kernel(const float* __restrict__ conv_w,
                            const float* __restrict__ conv_state,
                            const int* __restrict__ input_pos)
{
    __shared__ float srow[4096];   // q|k portion only; v written directly
    int bt = blockIdx.x;
    int b = bt / T_, t = bt % T_;
    int tid = threadIdx.x;
    float keep = (input_pos[0] == 0) ? 0.f : 1.f;

    for (int d = tid; d < CONV_DIM_; d += 256) {
        float4 w = *(const float4*)(conv_w + (long)d * 4);
        float acc = 0.f;
#pragma unroll
        for (int j = 0; j < 4; j++) {
            int tt = t - 3 + j;
            float xv;
            if (tt >= 0) xv = g_qkv[(long)(b * T_ + tt) * CONV_DIM_ + d];
            else         xv = keep * conv_state[((long)b * CONV_DIM_ + d) * 4 + (t + 1 + j)];
            float wj = (j == 0) ? w.x : (j == 1) ? w.y : (j == 2) ? w.z : w.w;
            acc += wj * xv;
        }
        float s = acc / (1.f + expf(-acc));     // silu
        if (d < 4096) srow[d] = s;
        else          g_v[(long)bt * VAL_DIM_ + (d - 4096)] = s;
    }
    __syncthreads();

    int lane = tid & 31, warp = tid >> 5;
    for (int s = warp; s < 32; s += 8) {         // 16 q-heads + 16 k-heads
        float vals[4]; float ss = 0.f;
#pragma unroll
        for (int j = 0; j < 4; j++) { vals[j] = srow[s * 128 + lane + 32 * j]; ss += vals[j] * vals[j]; }
#pragma unroll
        for (int off = 16; off; off >>= 1) ss += __shfl_xor_sync(0xffffffffu, ss, off);
        float inv = 1.f / fmaxf(sqrtf(ss), 1e-12f);
        float* dst = (s < 16) ? (g_q + (long)bt * KEY_DIM_ + s * 128)
                              : (g_k + (long)bt * KEY_DIM_ + (s - 16) * 128);
#pragma unroll
        for (int j = 0; j < 4; j++) dst[lane + 32 * j] = vals[j] * inv;
    }
}

// ---------------- chunked gated linear-attention recurrence ----------------
__device__ __forceinline__ void fma4(float4& a, float s, const float4 b)
{ a.x += s * b.x; a.y += s * b.y; a.z += s * b.z; a.w += s * b.w; }

__global__ void recur_kernel(const float* __restrict__ rstate, const int* __restrict__ input_pos)
{
    extern __shared__ float sm[];
    float* sq = sm;                  // 64*132
    float* sk = sq + 64 * 132;       // 64*132
    float* sv = sk + 64 * 132;       // 64*68
    float* sA = sv + 64 * 68;        // 64*68
    float* sS = sA + 64 * 68;        // 128*68
    float* sG = sS + 128 * 68;       // 64
    float* sB = sG + 64;             // 64
    float* sW = sB + 64;             // 64

    int bidx = blockIdx.x;
    int vs = bidx & 1;
    int h  = (bidx >> 1) & (NV_ - 1);
    int b  = bidx >> 6;
    int hk = h >> 1;                 // rep = NV/NK = 2
    int tid = threadIdx.x;
    int tx = tid & 15, ty = tid >> 4;
    float keep = (input_pos[0] == 0) ? 0.f : 1.f;

    // init state slice S[128][64]; thread owns rows ty*8..ty*8+7, cols tx*4..tx*4+3
#pragma unroll
    for (int j = 0; j < 8; j++) {
        int kk = ty * 8 + j;
        float4 v4 = *(const float4*)(rstate + (((long)(b * NV_ + h)) * DK_ + kk) * DV_ + vs * DVS + tx * 4);
        v4.x *= keep; v4.y *= keep; v4.z *= keep; v4.w *= keep;
        *(float4*)&sS[kk * 68 + tx * 4] = v4;
    }

    for (int ch = 0; ch < NCH; ch++) {
        int t0 = ch * LCH;
        __syncthreads();
        // load q,k [64][128]
        for (int f = tid; f < 64 * 32; f += 256) {
            int r = f >> 5, c = (f & 31) * 4;
            *(float4*)&sq[r * 132 + c] = *(const float4*)(g_q + (long)(b * T_ + t0 + r) * KEY_DIM_ + hk * DK_ + c);
            *(float4*)&sk[r * 132 + c] = *(const float4*)(g_k + (long)(b * T_ + t0 + r) * KEY_DIM_ + hk * DK_ + c);
        }
        // load v [64][64]
        for (int f = tid; f < 64 * 16; f += 256) {
            int r = f >> 4, c = (f & 15) * 4;
            *(float4*)&sv[r * 68 + c] = *(const float4*)(g_v + (long)(b * T_ + t0 + r) * VAL_DIM_ + h * DV_ + vs * DVS + c);
        }
        if (tid < 64) {
            sB[tid] = g_beta[(b * T_ + t0 + tid) * NV_ + h];
            sG[tid] = g_gg  [(b * T_ + t0 + tid) * NV_ + h];
        }
        __syncthreads();
        if (tid == 0) {                       // inclusive prefix of g
            float run = 0.f;
            for (int i = 0; i < LCH; i++) { run += sG[i]; sG[i] = run; }
        }
        __syncthreads();
        if (tid < 64) sW[tid] = expf(sG[63] - sG[tid]) * sB[tid];

        // A[t][i] = (q_t . k_i) * exp(G_t - G_i) * beta_i  for i<=t
        float accA[4][4];
#pragma unroll
        for (int a = 0; a < 4; a++)
#pragma unroll
            for (int c = 0; c < 4; c++) accA[a][c] = 0.f;
        for (int k4 = 0; k4 < DK_; k4 += 4) {
            float4 kb[4];
#pragma unroll
            for (int c = 0; c < 4; c++) kb[c] = *(float4*)&sk[(tx * 4 + c) * 132 + k4];
#pragma unroll
            for (int a = 0; a < 4; a++) {
                float4 qa = *(float4*)&sq[(ty * 4 + a) * 132 + k4];
#pragma unroll
                for (int c = 0; c < 4; c++)
                    accA[a][c] += qa.x * kb[c].x + qa.y * kb[c].y + qa.z * kb[c].z + qa.w * kb[c].w;
            }
        }
#pragma unroll
        for (int a = 0; a < 4; a++) {
            int t = ty * 4 + a; float gt = sG[t];
#pragma unroll
            for (int c = 0; c < 4; c++) {
                int i = tx * 4 + c;
                sA[t * 68 + i] = (i <= t) ? accA[a][c] * expf(gt - sG[i]) * sB[i] : 0.f;
            }
        }
        __syncthreads();

        // out[t][n] = (A @ V)[t][n] + exp(G_t) * (q_t . S[:,n])
        float4 acc[4], acci[4];
#pragma unroll
        for (int a = 0; a < 4; a++) { acc[a] = make_float4(0,0,0,0); acci[a] = make_float4(0,0,0,0); }
        for (int i4 = 0; i4 < LCH; i4 += 4) {
            float4 vv[4];
#pragma unroll
            for (int ii = 0; ii < 4; ii++) vv[ii] = *(float4*)&sv[(i4 + ii) * 68 + tx * 4];
#pragma unroll
            for (int a = 0; a < 4; a++) {
                float4 av = *(float4*)&sA[(ty * 4 + a) * 68 + i4];
                fma4(acc[a], av.x, vv[0]); fma4(acc[a], av.y, vv[1]);
                fma4(acc[a], av.z, vv[2]); fma4(acc[a], av.w, vv[3]);
            }
        }
        for (int k4 = 0; k4 < DK_; k4 += 4) {
            float4 ssr[4];
#pragma unroll
            for (int kk = 0; kk < 4; kk++) ssr[kk] = *(float4*)&sS[(k4 + kk) * 68 + tx * 4];
#pragma unroll
            for (int a = 0; a < 4; a++) {
                float4 qa = *(float4*)&sq[(ty * 4 + a) * 132 + k4];
                fma4(acci[a], qa.x, ssr[0]); fma4(acci[a], qa.y, ssr[1]);
                fma4(acci[a], qa.z, ssr[2]); fma4(acci[a], qa.w, ssr[3]);
            }
        }
#pragma unroll
        for (int a = 0; a < 4; a++) {
            int t = ty * 4 + a;
            float et = expf(sG[t]);
            float4 w4 = make_float4(acc[a].x + et * acci[a].x, acc[a].y + et * acci[a].y,
                                    acc[a].z + et * acci[a].z, acc[a].w + et * acci[a].w);
            *(float4*)(g_o + (long)(b * T_ + t0 + t) * VAL_DIM_ + h * DV_ + vs * DVS + tx * 4) = w4;
        }
        __syncthreads();

        // S = exp(G_last)*S + sum_i w_i * k_i (outer) v_i
        float elast = expf(sG[63]);
        float4 Sreg[8];
#pragma unroll
        for (int j = 0; j < 8; j++) {
            Sreg[j] = *(float4*)&sS[(ty * 8 + j) * 68 + tx * 4];
            Sreg[j].x *= elast; Sreg[j].y *= elast; Sreg[j].z *= elast; Sreg[j].w *= elast;
        }
        for (int i = 0; i < LCH; i++) {
            float w = sW[i];
            float4 vv = *(float4*)&sv[i * 68 + tx * 4];
            float4 k0 = *(float4*)&sk[i * 132 + ty * 8];
            float4 k1 = *(float4*)&sk[i * 132 + ty * 8 + 4];
            fma4(Sreg[0], w * k0.x, vv); fma4(Sreg[1], w * k0.y, vv);
            fma4(Sreg[2], w * k0.z, vv); fma4(Sreg[3], w * k0.w, vv);
            fma4(Sreg[4], w * k1.x, vv); fma4(Sreg[5], w * k1.y, vv);
            fma4(Sreg[6], w * k1.z, vv); fma4(Sreg[7], w * k1.w, vv);
        }
#pragma unroll
        for (int j = 0; j < 8; j++)
            *(float4*)&sS[(ty * 8 + j) * 68 + tx * 4] = Sreg[j];
    }
}

// ---------------- gated RMSNorm: o = rmsnorm(o * silu(z)) * norm_w ----------------
__global__ void rmsnorm_kernel(const float* __restrict__ norm_w)
{
    int bh = blockIdx.x;
    int bt = bh >> 5, h = bh & 31;
    int tid = threadIdx.x;          // 128
    long idx = (long)bt * VAL_DIM_ + h * DV_ + tid;
    float o = g_o[idx];
    float z = g_z[idx];
    float val = o * (z / (1.f + expf(-z)));
    float s = val * val;
#pragma unroll
    for (int off = 16; off; off >>= 1) s += __shfl_xor_sync(0xffffffffu, s, off);
    __shared__ float red[4];
    int warp = tid >> 5, lane = tid & 31;
    if (lane == 0) red[warp] = s;
    __syncthreads();
    float tot = red[0] + red[1] + red[2] + red[3];
    float scale = rsqrtf(tot * (1.f / 128.f) + 1e-6f) * norm_w[tid];
    g_o[idx] = val * scale;
}

// ---------------- launch ----------------
extern "C" void kernel_launch(void* const* d_in, const int* in_sizes, int n_in,
                              void* d_out, int out_size)
{
    const float* x          = (const float*)d_in[0];
    const int*   input_pos  = (const int*)  d_in[1];
    const float* W_qkv      = (const float*)d_in[2];
    const float* W_z        = (const float*)d_in[3];
    const float* W_b        = (const float*)d_in[4];
    const float* W_a        = (const float*)d_in[5];
    const float* conv_w     = (const float*)d_in[6];
    const float* dt_bias    = (const float*)d_in[7];
    const float* A_log      = (const float*)d_in[8];
    const float* norm_w     = (const float*)d_in[9];
    const float* W_out      = (const float*)d_in[10];
    const float* conv_state = (const float*)d_in[11];
    const float* rstate     = (const float*)d_in[12];
    float* out = (float*)d_out;

    float *p_qkv, *p_z, *p_braw, *p_araw, *p_o;
    cudaGetSymbolAddress((void**)&p_qkv,  g_qkv);
    cudaGetSymbolAddress((void**)&p_z,    g_z);
    cudaGetSymbolAddress((void**)&p_braw, g_braw);
    cudaGetSymbolAddress((void**)&p_araw, g_araw);
    cudaGetSymbolAddress((void**)&p_o,    g_o);

    const int RECUR_SMEM = (64*132*2 + 64*68*2 + 128*68 + 64*3) * 4;   // 137984 B
    cudaFuncSetAttribute(recur_kernel, cudaFuncAttributeMaxDynamicSharedMemorySize, RECUR_SMEM);

    sgemm_nt<<<dim3(64, 32), 256>>>(x, W_qkv, p_qkv, BT_, CONV_DIM_, C_);
    sgemm_nt<<<dim3(32, 32), 256>>>(x, W_z,   p_z,   BT_, VAL_DIM_,  C_);
    sgemm_nt<<<dim3(1, 32),  256>>>(x, W_b,   p_braw, BT_, NV_, C_);
    sgemm_nt<<<dim3(1, 32),  256>>>(x, W_a,   p_araw, BT_, NV_, C_);
    betag_kernel<<<(BT_ * NV_ + 255) / 256, 256>>>(dt_bias, A_log);
    conv_kernel<<<BT_, 256>>>(conv_w, conv_state, input_pos);
    recur_kernel<<<B_ * NV_ * SPLITV, 256, RECUR_SMEM>>>(rstate, input_pos);
    rmsnorm_kernel<<<BT_ * NV_, 128>>>(norm_w);
    sgemm_nt<<<dim3(16, 32), 256>>>(p_o, W_out, out, BT_, C_, VAL_DIM_);
}

// round 3
// speedup vs baseline: 4.1490x; 4.1490x over previous
#include <cuda_runtime.h>
#include <cuda_fp16.h>
#include <math.h>
#include <stdint.h>

#define B_ 2
#define T_ 2048
#define C_ 2048
#define NV_ 32
#define DK_ 128
#define DV_ 128
#define KEY_DIM_ 2048
#define VAL_DIM_ 4096
#define CONV_DIM_ 8192
#define BT_ (B_*T_)
#define LCH 64
#define NCH (T_/LCH)
#define SPLITV 2
#define DVS (DV_/SPLITV)

// ---------------- scratch (static device globals; no allocation) ----------------
__device__ float g_qkv [BT_*CONV_DIM_];
__device__ float g_z   [BT_*VAL_DIM_];
__device__ float g_q   [BT_*KEY_DIM_];
__device__ float g_k   [BT_*KEY_DIM_];
__device__ float g_v   [BT_*VAL_DIM_];
__device__ float g_ba  [BT_*64];
__device__ float g_beta[BT_*NV_];
__device__ float g_gg  [BT_*NV_];
__device__ float g_o   [BT_*VAL_DIM_];

__device__ __half g_xh [BT_*C_];
__device__ __half g_Wqh[CONV_DIM_*C_];
__device__ __half g_Wzh[VAL_DIM_*C_];
__device__ __half g_Woh[C_*VAL_DIM_];
__device__ __half g_oh [BT_*VAL_DIM_];

// ---------------- helpers ----------------
__device__ __forceinline__ uint32_t smem_u32(const void* p) {
    uint32_t a;
    asm("{ .reg .u64 t; cvta.to.shared.u64 t, %1; cvt.u32.u64 %0, t; }" : "=r"(a) : "l"(p));
    return a;
}
__device__ __forceinline__ void ldsm_x4(uint32_t& r0, uint32_t& r1, uint32_t& r2, uint32_t& r3, uint32_t addr) {
    asm volatile("ldmatrix.sync.aligned.m8n8.x4.shared.b16 {%0,%1,%2,%3}, [%4];"
                 : "=r"(r0), "=r"(r1), "=r"(r2), "=r"(r3) : "r"(addr));
}
__device__ __forceinline__ void mma16816(float* c, uint32_t a0, uint32_t a1, uint32_t a2, uint32_t a3,
                                         uint32_t b0, uint32_t b1) {
    asm volatile("mma.sync.aligned.m16n8k16.row.col.f32.f16.f16.f32 "
                 "{%0,%1,%2,%3}, {%4,%5,%6,%7}, {%8,%9}, {%0,%1,%2,%3};"
                 : "+f"(c[0]), "+f"(c[1]), "+f"(c[2]), "+f"(c[3])
                 : "r"(a0), "r"(a1), "r"(a2), "r"(a3), "r"(b0), "r"(b1));
}

// ---------------- fp16 HGEMM: C[M,N] = A[M,K] * B[N,K]^T (row-major, fp32 accum) ----------------
// block tile 128x128, K-tile 32, 8 warps (2 M x 4 N), warp tile 64x32, double-buffered.
__global__ __launch_bounds__(256, 2)
void hgemm_nt(const __half* __restrict__ A, const __half* __restrict__ Bm,
              float* __restrict__ C, int M, int N, int K)
{
    __shared__ __half As[2][128][40];
    __shared__ __half Bs[2][128][40];

    int tid = threadIdx.x;
    int lane = tid & 31, wid = tid >> 5;
    int wm = wid & 1, wn = wid >> 1;          // 2 x 4 warp grid
    int m0w = wm * 64, n0w = wn * 32;
    int row0 = blockIdx.y * 128, col0 = blockIdx.x * 128;

    uint32_t asBase = smem_u32(&As[0][0][0]);
    uint32_t bsBase = smem_u32(&Bs[0][0][0]);

    float acc[4][4][4];
#pragma unroll
    for (int i = 0; i < 4; i++)
#pragma unroll
        for (int j = 0; j < 4; j++)
#pragma unroll
            for (int e = 0; e < 4; e++) acc[i][j][e] = 0.f;

    const int NT = K >> 5;
    int r0 = tid >> 2, c0 = (tid & 3) << 3;   // loader coords: 64 rows per half-warp-group
    int r1 = r0 + 64;

    // preload tile 0
    {
        const __half* ap = A + (size_t)(row0 + r0) * K + c0;
        const __half* ap1 = A + (size_t)(row0 + r1) * K + c0;
        const __half* bp = Bm + (size_t)(col0 + r0) * K + c0;
        const __half* bp1 = Bm + (size_t)(col0 + r1) * K + c0;
        *(uint4*)&As[0][r0][c0] = *(const uint4*)ap;
        *(uint4*)&As[0][r1][c0] = *(const uint4*)ap1;
        *(uint4*)&Bs[0][r0][c0] = *(const uint4*)bp;
        *(uint4*)&Bs[0][r1][c0] = *(const uint4*)bp1;
    }
    __syncthreads();

    int buf = 0;
    for (int kt = 0; kt < NT; kt++) {
        uint4 la, la1, lb, lb1;
        if (kt + 1 < NT) {
            int k0 = (kt + 1) << 5;
            la  = *(const uint4*)(A + (size_t)(row0 + r0) * K + k0 + c0);
            la1 = *(const uint4*)(A + (size_t)(row0 + r1) * K + k0 + c0);
            lb  = *(const uint4*)(Bm + (size_t)(col0 + r0) * K + k0 + c0);
            lb1 = *(const uint4*)(Bm + (size_t)(col0 + r1) * K + k0 + c0);
        }
#pragma unroll
        for (int kk = 0; kk < 32; kk += 16) {
            uint32_t a[4][4], b[4][2];
#pragma unroll
            for (int i = 0; i < 4; i++) {
                int r = m0w + i * 16 + (lane & 15);
                int c = kk + ((lane >> 4) << 3);
                ldsm_x4(a[i][0], a[i][1], a[i][2], a[i][3],
                        asBase + (((buf * 128 + r) * 40 + c) << 1));
            }
#pragma unroll
            for (int j = 0; j < 2; j++) {
                int q = lane >> 3, rr = lane & 7;
                int r = n0w + j * 16 + ((q >> 1) << 3) + rr;
                int c = kk + ((q & 1) << 3);
                uint32_t t0, t1, t2, t3;
                ldsm_x4(t0, t1, t2, t3, bsBase + (((buf * 128 + r) * 40 + c) << 1));
                b[2*j][0] = t0; b[2*j][1] = t1; b[2*j+1][0] = t2; b[2*j+1][1] = t3;
            }
#pragma unroll
            for (int i = 0; i < 4; i++)
#pragma unroll
                for (int j = 0; j < 4; j++)
                    mma16816(acc[i][j], a[i][0], a[i][1], a[i][2], a[i][3], b[j][0], b[j][1]);
        }
        if (kt + 1 < NT) {
            int nb = buf ^ 1;
            *(uint4*)&As[nb][r0][c0] = la;
            *(uint4*)&As[nb][r1][c0] = la1;
            *(uint4*)&Bs[nb][r0][c0] = lb;
            *(uint4*)&Bs[nb][r1][c0] = lb1;
            __syncthreads();
            buf = nb;
        }
    }

    // epilogue
#pragma unroll
    for (int i = 0; i < 4; i++) {
        int r = row0 + m0w + i * 16 + (lane >> 2);
#pragma unroll
        for (int j = 0; j < 4; j++) {
            int c = col0 + n0w + j * 8 + ((lane & 3) << 1);
            *(float2*)&C[(size_t)r * N + c]       = make_float2(acc[i][j][0], acc[i][j][1]);
            *(float2*)&C[(size_t)(r + 8) * N + c] = make_float2(acc[i][j][2], acc[i][j][3]);
        }
    }
}

// ---------------- fp32 -> fp16 convert ----------------
__global__ void cvt_half(const float* __restrict__ in, __half* __restrict__ out, int n4)
{
    int i = blockIdx.x * blockDim.x + threadIdx.x;
    if (i >= n4) return;
    float4 v = ((const float4*)in)[i];
    union { __half h[4]; uint2 u; } p;
    p.h[0] = __float2half_rn(v.x); p.h[1] = __float2half_rn(v.y);
    p.h[2] = __float2half_rn(v.z); p.h[3] = __float2half_rn(v.w);
    ((uint2*)out)[i] = p.u;
}

__global__ void zero_kernel(float* p, int n)
{
    int i = blockIdx.x * blockDim.x + threadIdx.x;
    if (i < n) p[i] = 0.f;
}

// ---------------- fp32 split-K GEMM for b|a:  C[M,64] += A[M,K] * B[64,K]^T ----------------
__global__ void sgemm_ba(const float* __restrict__ A, const float* __restrict__ Wb,
                         const float* __restrict__ Wa, float* __restrict__ C, int M, int K)
{
    __shared__ float As[16][128];
    __shared__ float Bs[16][64];
    int tid = threadIdx.x;
    int tx = tid & 15, ty = tid >> 4;
    int row0 = blockIdx.y * 128;
    int kBeg = blockIdx.z * (K / 8), kEnd = kBeg + K / 8;

    float acc[8][4];
#pragma unroll
    for (int m = 0; m < 8; m++)
#pragma unroll
        for (int n = 0; n < 4; n++) acc[m][n] = 0.f;

    for (int kt = kBeg; kt < kEnd; kt += 16) {
#pragma unroll
        for (int i = 0; i < 2; i++) {
            int f = tid + i * 256;
            int r = f >> 2, c4 = (f & 3) << 2;
            float4 av = *(const float4*)(A + (size_t)(row0 + r) * K + kt + c4);
            As[c4][r] = av.x; As[c4+1][r] = av.y; As[c4+2][r] = av.z; As[c4+3][r] = av.w;
        }
        if (tid < 256) {
            int r = tid >> 2, c4 = (tid & 3) << 2;
            if (r < 64) {
                const float* src = (r < 32) ? (Wb + (size_t)r * K) : (Wa + (size_t)(r - 32) * K);
                float4 bv = *(const float4*)(src + kt + c4);
                Bs[c4][r] = bv.x; Bs[c4+1][r] = bv.y; Bs[c4+2][r] = bv.z; Bs[c4+3][r] = bv.w;
            }
        }
        __syncthreads();
#pragma unroll
        for (int k = 0; k < 16; k++) {
            float ra[8], rb[4];
            *(float4*)&ra[0] = *(float4*)&As[k][ty * 8];
            *(float4*)&ra[4] = *(float4*)&As[k][ty * 8 + 4];
            *(float4*)&rb[0] = *(float4*)&Bs[k][tx * 4];
#pragma unroll
            for (int m = 0; m < 8; m++)
#pragma unroll
                for (int n = 0; n < 4; n++) acc[m][n] += ra[m] * rb[n];
        }
        __syncthreads();
    }
#pragma unroll
    for (int m = 0; m < 8; m++) {
        int gr = row0 + ty * 8 + m;
#pragma unroll
        for (int n = 0; n < 4; n++)
            atomicAdd(&C[(size_t)gr * 64 + tx * 4 + n], acc[m][n]);
    }
}

// ---------------- beta / g finalize ----------------
__global__ void betag_kernel(const float* __restrict__ dt_bias, const float* __restrict__ A_log)
{
    int i = blockIdx.x * blockDim.x + threadIdx.x;
    if (i >= BT_ * NV_) return;
    int bt = i >> 5, h = i & 31;
    float braw = g_ba[bt * 64 + h];
    float araw = g_ba[bt * 64 + 32 + h];
    g_beta[i] = 1.f / (1.f + expf(-braw));
    float a = araw + dt_bias[h];
    float sp = (a > 20.f) ? a : log1pf(expf(a));
    g_gg[i] = -expf(A_log[h]) * sp;
}

// ---------------- causal depthwise conv(K=4) + silu + q/k L2 norm ----------------
__global__ void conv_kernel(const float* __restrict__ conv_w,
                            const float* __restrict__ conv_state,
                            const int* __restrict__ input_pos)
{
    __shared__ float srow[4096];
    int bt = blockIdx.x;
    int b = bt / T_, t = bt % T_;
    int tid = threadIdx.x;
    float keep = (input_pos[0] == 0) ? 0.f : 1.f;

    for (int d = tid; d < CONV_DIM_; d += 256) {
        float4 w = *(const float4*)(conv_w + (long)d * 4);
        float acc = 0.f;
#pragma unroll
        for (int j = 0; j < 4; j++) {
            int tt = t - 3 + j;
            float xv;
            if (tt >= 0) xv = g_qkv[(long)(b * T_ + tt) * CONV_DIM_ + d];
            else         xv = keep * conv_state[((long)b * CONV_DIM_ + d) * 4 + (t + 1 + j)];
            float wj = (j == 0) ? w.x : (j == 1) ? w.y : (j == 2) ? w.z : w.w;
            acc += wj * xv;
        }
        float s = acc / (1.f + expf(-acc));
        if (d < 4096) srow[d] = s;
        else          g_v[(long)bt * VAL_DIM_ + (d - 4096)] = s;
    }
    __syncthreads();

    int lane = tid & 31, warp = tid >> 5;
    for (int s = warp; s < 32; s += 8) {
        float vals[4]; float ss = 0.f;
#pragma unroll
        for (int j = 0; j < 4; j++) { vals[j] = srow[s * 128 + lane + 32 * j]; ss += vals[j] * vals[j]; }
#pragma unroll
        for (int off = 16; off; off >>= 1) ss += __shfl_xor_sync(0xffffffffu, ss, off);
        float inv = 1.f / fmaxf(sqrtf(ss), 1e-12f);
        float* dst = (s < 16) ? (g_q + (long)bt * KEY_DIM_ + s * 128)
                              : (g_k + (long)bt * KEY_DIM_ + (s - 16) * 128);
#pragma unroll
        for (int j = 0; j < 4; j++) dst[lane + 32 * j] = vals[j] * inv;
    }
}

// ---------------- chunked gated linear-attention recurrence ----------------
__device__ __forceinline__ void fma4(float4& a, float s, const float4 b)
{ a.x += s * b.x; a.y += s * b.y; a.z += s * b.z; a.w += s * b.w; }

__global__ void recur_kernel(const float* __restrict__ rstate, const int* __restrict__ input_pos)
{
    extern __shared__ float sm[];
    float* sq = sm;
    float* sk = sq + 64 * 132;
    float* sv = sk + 64 * 132;
    float* sA = sv + 64 * 68;
    float* sS = sA + 64 * 68;
    float* sG = sS + 128 * 68;
    float* sB = sG + 64;
    float* sW = sB + 64;

    int bidx = blockIdx.x;
    int vs = bidx & 1;
    int h  = (bidx >> 1) & (NV_ - 1);
    int b  = bidx >> 6;
    int hk = h >> 1;
    int tid = threadIdx.x;
    int tx = tid & 15, ty = tid >> 4;
    float keep = (input_pos[0] == 0) ? 0.f : 1.f;

#pragma unroll
    for (int j = 0; j < 8; j++) {
        int kk = ty * 8 + j;
        float4 v4 = *(const float4*)(rstate + (((long)(b * NV_ + h)) * DK_ + kk) * DV_ + vs * DVS + tx * 4);
        v4.x *= keep; v4.y *= keep; v4.z *= keep; v4.w *= keep;
        *(float4*)&sS[kk * 68 + tx * 4] = v4;
    }

    for (int ch = 0; ch < NCH; ch++) {
        int t0 = ch * LCH;
        __syncthreads();
        for (int f = tid; f < 64 * 32; f += 256) {
            int r = f >> 5, c = (f & 31) * 4;
            *(float4*)&sq[r * 132 + c] = *(const float4*)(g_q + (long)(b * T_ + t0 + r) * KEY_DIM_ + hk * DK_ + c);
            *(float4*)&sk[r * 132 + c] = *(const float4*)(g_k + (long)(b * T_ + t0 + r) * KEY_DIM_ + hk * DK_ + c);
        }
        for (int f = tid; f < 64 * 16; f += 256) {
            int r = f >> 4, c = (f & 15) * 4;
            *(float4*)&sv[r * 68 + c] = *(const float4*)(g_v + (long)(b * T_ + t0 + r) * VAL_DIM_ + h * DV_ + vs * DVS + c);
        }
        if (tid < 64) {
            sB[tid] = g_beta[(b * T_ + t0 + tid) * NV_ + h];
            sG[tid] = g_gg  [(b * T_ + t0 + tid) * NV_ + h];
        }
        __syncthreads();
        if (tid == 0) {
            float run = 0.f;
            for (int i = 0; i < LCH; i++) { run += sG[i]; sG[i] = run; }
        }
        __syncthreads();
        if (tid < 64) sW[tid] = expf(sG[63] - sG[tid]) * sB[tid];

        float accA[4][4];
#pragma unroll
        for (int a = 0; a < 4; a++)
#pragma unroll
            for (int c = 0; c < 4; c++) accA[a][c] = 0.f;
        for (int k4 = 0; k4 < DK_; k4 += 4) {
            float4 kb[4];
#pragma unroll
            for (int c = 0; c < 4; c++) kb[c] = *(float4*)&sk[(tx * 4 + c) * 132 + k4];
#pragma unroll
            for (int a = 0; a < 4; a++) {
                float4 qa = *(float4*)&sq[(ty * 4 + a) * 132 + k4];
#pragma unroll
                for (int c = 0; c < 4; c++)
                    accA[a][c] += qa.x * kb[c].x + qa.y * kb[c].y + qa.z * kb[c].z + qa.w * kb[c].w;
            }
        }
#pragma unroll
        for (int a = 0; a < 4; a++) {
            int t = ty * 4 + a; float gt = sG[t];
#pragma unroll
            for (int c = 0; c < 4; c++) {
                int i = tx * 4 + c;
                sA[t * 68 + i] = (i <= t) ? accA[a][c] * expf(gt - sG[i]) * sB[i] : 0.f;
            }
        }
        __syncthreads();

        float4 acc[4], acci[4];
#pragma unroll
        for (int a = 0; a < 4; a++) { acc[a] = make_float4(0,0,0,0); acci[a] = make_float4(0,0,0,0); }
        for (int i4 = 0; i4 < LCH; i4 += 4) {
            float4 vv[4];
#pragma unroll
            for (int ii = 0; ii < 4; ii++) vv[ii] = *(float4*)&sv[(i4 + ii) * 68 + tx * 4];
#pragma unroll
            for (int a = 0; a < 4; a++) {
                float4 av = *(float4*)&sA[(ty * 4 + a) * 68 + i4];
                fma4(acc[a], av.x, vv[0]); fma4(acc[a], av.y, vv[1]);
                fma4(acc[a], av.z, vv[2]); fma4(acc[a], av.w, vv[3]);
            }
        }
        for (int k4 = 0; k4 < DK_; k4 += 4) {
            float4 ssr[4];
#pragma unroll
            for (int kk = 0; kk < 4; kk++) ssr[kk] = *(float4*)&sS[(k4 + kk) * 68 + tx * 4];
#pragma unroll
            for (int a = 0; a < 4; a++) {
                float4 qa = *(float4*)&sq[(ty * 4 + a) * 132 + k4];
                fma4(acci[a], qa.x, ssr[0]); fma4(acci[a], qa.y, ssr[1]);
                fma4(acci[a], qa.z, ssr[2]); fma4(acci[a], qa.w, ssr[3]);
            }
        }
#pragma unroll
        for (int a = 0; a < 4; a++) {
            int t = ty * 4 + a;
            float et = expf(sG[t]);
            float4 w4 = make_float4(acc[a].x + et * acci[a].x, acc[a].y + et * acci[a].y,
                                    acc[a].z + et * acci[a].z, acc[a].w + et * acci[a].w);
            *(float4*)(g_o + (long)(b * T_ + t0 + t) * VAL_DIM_ + h * DV_ + vs * DVS + tx * 4) = w4;
        }
        __syncthreads();

        float elast = expf(sG[63]);
        float4 Sreg[8];
#pragma unroll
        for (int j = 0; j < 8; j++) {
            Sreg[j] = *(float4*)&sS[(ty * 8 + j) * 68 + tx * 4];
            Sreg[j].x *= elast; Sreg[j].y *= elast; Sreg[j].z *= elast; Sreg[j].w *= elast;
        }
        for (int i = 0; i < LCH; i++) {
            float w = sW[i];
            float4 vv = *(float4*)&sv[i * 68 + tx * 4];
            float4 k0 = *(float4*)&sk[i * 132 + ty * 8];
            float4 k1 = *(float4*)&sk[i * 132 + ty * 8 + 4];
            fma4(Sreg[0], w * k0.x, vv); fma4(Sreg[1], w * k0.y, vv);
            fma4(Sreg[2], w * k0.z, vv); fma4(Sreg[3], w * k0.w, vv);
            fma4(Sreg[4], w * k1.x, vv); fma4(Sreg[5], w * k1.y, vv);
            fma4(Sreg[6], w * k1.z, vv); fma4(Sreg[7], w * k1.w, vv);
        }
#pragma unroll
        for (int j = 0; j < 8; j++)
            *(float4*)&sS[(ty * 8 + j) * 68 + tx * 4] = Sreg[j];
    }
}

// ---------------- gated RMSNorm -> fp16 ----------------
__global__ void rmsnorm_kernel(const float* __restrict__ norm_w)
{
    int bh = blockIdx.x;
    int bt = bh >> 5, h = bh & 31;
    int tid = threadIdx.x;          // 128
    long idx = (long)bt * VAL_DIM_ + h * DV_ + tid;
    float o = g_o[idx];
    float z = g_z[idx];
    float val = o * (z / (1.f + expf(-z)));
    float s = val * val;
#pragma unroll
    for (int off = 16; off; off >>= 1) s += __shfl_xor_sync(0xffffffffu, s, off);
    __shared__ float red[4];
    int warp = tid >> 5, lane = tid & 31;
    if (lane == 0) red[warp] = s;
    __syncthreads();
    float tot = red[0] + red[1] + red[2] + red[3];
    float scale = rsqrtf(tot * (1.f / 128.f) + 1e-6f) * norm_w[tid];
    g_oh[idx] = __float2half_rn(val * scale);
}

// ---------------- launch ----------------
extern "C" void kernel_launch(void* const* d_in, const int* in_sizes, int n_in,
                              void* d_out, int out_size)
{
    const float* x          = (const float*)d_in[0];
    const int*   input_pos  = (const int*)  d_in[1];
    const float* W_qkv      = (const float*)d_in[2];
    const float* W_z        = (const float*)d_in[3];
    const float* W_b        = (const float*)d_in[4];
    const float* W_a        = (const float*)d_in[5];
    const float* conv_w     = (const float*)d_in[6];
    const float* dt_bias    = (const float*)d_in[7];
    const float* A_log      = (const float*)d_in[8];
    const float* norm_w     = (const float*)d_in[9];
    const float* W_out      = (const float*)d_in[10];
    const float* conv_state = (const float*)d_in[11];
    const float* rstate     = (const float*)d_in[12];
    float* out = (float*)d_out;

    float *p_qkv, *p_z, *p_ba;
    __half *p_xh, *p_Wqh, *p_Wzh, *p_Woh, *p_oh;
    cudaGetSymbolAddress((void**)&p_qkv, g_qkv);
    cudaGetSymbolAddress((void**)&p_z,   g_z);
    cudaGetSymbolAddress((void**)&p_ba,  g_ba);
    cudaGetSymbolAddress((void**)&p_xh,  g_xh);
    cudaGetSymbolAddress((void**)&p_Wqh, g_Wqh);
    cudaGetSymbolAddress((void**)&p_Wzh, g_Wzh);
    cudaGetSymbolAddress((void**)&p_Woh, g_Woh);
    cudaGetSymbolAddress((void**)&p_oh,  g_oh);

    const int RECUR_SMEM = (64*132*2 + 64*68*2 + 128*68 + 64*3) * 4;
    cudaFuncSetAttribute(recur_kernel, cudaFuncAttributeMaxDynamicSharedMemorySize, RECUR_SMEM);

    // fp32 -> fp16 conversions
    cvt_half<<<(BT_*C_/4 + 255)/256, 256>>>(x, p_xh, BT_*C_/4);
    cvt_half<<<(CONV_DIM_*C_/4 + 255)/256, 256>>>(W_qkv, p_Wqh, CONV_DIM_*C_/4);
    cvt_half<<<(VAL_DIM_*C_/4 + 255)/256, 256>>>(W_z, p_Wzh, VAL_DIM_*C_/4);
    cvt_half<<<(C_*VAL_DIM_/4 + 255)/256, 256>>>(W_out, p_Woh, C_*VAL_DIM_/4);

    // projections (fp16 tensor cores, fp32 accumulate)
    hgemm_nt<<<dim3(CONV_DIM_/128, BT_/128), 256>>>(p_xh, p_Wqh, p_qkv, BT_, CONV_DIM_, C_);
    hgemm_nt<<<dim3(VAL_DIM_/128, BT_/128), 256>>>(p_xh, p_Wzh, p_z, BT_, VAL_DIM_, C_);

    // b|a projection in fp32 (error amplified through gates; keep precise), split-K
    zero_kernel<<<(BT_*64 + 255)/256, 256>>>(p_ba, BT_*64);
    sgemm_ba<<<dim3(1, BT_/128, 8), 256>>>(x, W_b, W_a, p_ba, BT_, C_);

    betag_kernel<<<(BT_ * NV_ + 255) / 256, 256>>>(dt_bias, A_log);
    conv_kernel<<<BT_, 256>>>(conv_w, conv_state, input_pos);
    recur_kernel<<<B_ * NV_ * SPLITV, 256, RECUR_SMEM>>>(rstate, input_pos);
    rmsnorm_kernel<<<BT_ * NV_, 128>>>(norm_w);

    hgemm_nt<<<dim3(C_/128, BT_/128), 256>>>(p_oh, p_Woh, out, BT_, C_, VAL_DIM_);
}

// round 4
// speedup vs baseline: 4.2231x; 1.0179x over previous
#include <cuda_runtime.h>
#include <cuda_fp16.h>
#include <math.h>
#include <stdint.h>

#define B_ 2
#define T_ 2048
#define C_ 2048
#define NV_ 32
#define DK_ 128
#define DV_ 128
#define KEY_DIM_ 2048
#define VAL_DIM_ 4096
#define CONV_DIM_ 8192
#define BT_ (B_*T_)
#define LCH 64
#define NCH (T_/LCH)
#define SPLITV 2
#define DVS (DV_/SPLITV)

// ---------------- scratch (static device globals; no allocation) ----------------
__device__ float g_qkv [BT_*CONV_DIM_];
__device__ float g_z   [BT_*VAL_DIM_];
__device__ float g_q   [BT_*KEY_DIM_];
__device__ float g_k   [BT_*KEY_DIM_];
__device__ float g_v   [BT_*VAL_DIM_];
__device__ float g_ba  [BT_*64];
__device__ float g_beta[BT_*NV_];
__device__ float g_gg  [BT_*NV_];
__device__ float g_o   [BT_*VAL_DIM_];

__device__ __half g_xh [BT_*C_];
__device__ __half g_Wqh[CONV_DIM_*C_];
__device__ __half g_Wzh[VAL_DIM_*C_];
__device__ __half g_Woh[C_*VAL_DIM_];
__device__ __half g_oh [BT_*VAL_DIM_];

// ---------------- helpers ----------------
__device__ __forceinline__ uint32_t smem_u32(const void* p) {
    uint32_t a;
    asm("{ .reg .u64 t; cvta.to.shared.u64 t, %1; cvt.u32.u64 %0, t; }" : "=r"(a) : "l"(p));
    return a;
}
__device__ __forceinline__ void ldsm_x4(uint32_t& r0, uint32_t& r1, uint32_t& r2, uint32_t& r3, uint32_t addr) {
    asm volatile("ldmatrix.sync.aligned.m8n8.x4.shared.b16 {%0,%1,%2,%3}, [%4];"
                 : "=r"(r0), "=r"(r1), "=r"(r2), "=r"(r3) : "r"(addr));
}
__device__ __forceinline__ void mma16816(float* c, uint32_t a0, uint32_t a1, uint32_t a2, uint32_t a3,
                                         uint32_t b0, uint32_t b1) {
    asm volatile("mma.sync.aligned.m16n8k16.row.col.f32.f16.f16.f32 "
                 "{%0,%1,%2,%3}, {%4,%5,%6,%7}, {%8,%9}, {%0,%1,%2,%3};"
                 : "+f"(c[0]), "+f"(c[1]), "+f"(c[2]), "+f"(c[3])
                 : "r"(a0), "r"(a1), "r"(a2), "r"(a3), "r"(b0), "r"(b1));
}

// ---------------- fp16 HGEMM: C[M,N] = A[M,K] * B[N,K]^T (row-major, fp32 accum) ----------------
__global__ __launch_bounds__(256, 2)
void hgemm_nt(const __half* __restrict__ A, const __half* __restrict__ Bm,
              float* __restrict__ C, int M, int N, int K)
{
    __shared__ __half As[2][128][40];
    __shared__ __half Bs[2][128][40];

    int tid = threadIdx.x;
    int lane = tid & 31, wid = tid >> 5;
    int wm = wid & 1, wn = wid >> 1;
    int m0w = wm * 64, n0w = wn * 32;
    int row0 = blockIdx.y * 128, col0 = blockIdx.x * 128;

    uint32_t asBase = smem_u32(&As[0][0][0]);
    uint32_t bsBase = smem_u32(&Bs[0][0][0]);

    float acc[4][4][4];
#pragma unroll
    for (int i = 0; i < 4; i++)
#pragma unroll
        for (int j = 0; j < 4; j++)
#pragma unroll
            for (int e = 0; e < 4; e++) acc[i][j][e] = 0.f;

    const int NT = K >> 5;
    int r0 = tid >> 2, c0 = (tid & 3) << 3;
    int r1 = r0 + 64;

    {
        *(uint4*)&As[0][r0][c0] = *(const uint4*)(A + (size_t)(row0 + r0) * K + c0);
        *(uint4*)&As[0][r1][c0] = *(const uint4*)(A + (size_t)(row0 + r1) * K + c0);
        *(uint4*)&Bs[0][r0][c0] = *(const uint4*)(Bm + (size_t)(col0 + r0) * K + c0);
        *(uint4*)&Bs[0][r1][c0] = *(const uint4*)(Bm + (size_t)(col0 + r1) * K + c0);
    }
    __syncthreads();

    int buf = 0;
    for (int kt = 0; kt < NT; kt++) {
        uint4 la, la1, lb, lb1;
        if (kt + 1 < NT) {
            int k0 = (kt + 1) << 5;
            la  = *(const uint4*)(A + (size_t)(row0 + r0) * K + k0 + c0);
            la1 = *(const uint4*)(A + (size_t)(row0 + r1) * K + k0 + c0);
            lb  = *(const uint4*)(Bm + (size_t)(col0 + r0) * K + k0 + c0);
            lb1 = *(const uint4*)(Bm + (size_t)(col0 + r1) * K + k0 + c0);
        }
#pragma unroll
        for (int kk = 0; kk < 32; kk += 16) {
            uint32_t a[4][4], b[4][2];
#pragma unroll
            for (int i = 0; i < 4; i++) {
                int r = m0w + i * 16 + (lane & 15);
                int c = kk + ((lane >> 4) << 3);
                ldsm_x4(a[i][0], a[i][1], a[i][2], a[i][3],
                        asBase + (((buf * 128 + r) * 40 + c) << 1));
            }
#pragma unroll
            for (int j = 0; j < 2; j++) {
                int q = lane >> 3, rr = lane & 7;
                int r = n0w + j * 16 + ((q >> 1) << 3) + rr;
                int c = kk + ((q & 1) << 3);
                uint32_t t0, t1, t2, t3;
                ldsm_x4(t0, t1, t2, t3, bsBase + (((buf * 128 + r) * 40 + c) << 1));
                b[2*j][0] = t0; b[2*j][1] = t1; b[2*j+1][0] = t2; b[2*j+1][1] = t3;
            }
#pragma unroll
            for (int i = 0; i < 4; i++)
#pragma unroll
                for (int j = 0; j < 4; j++)
                    mma16816(acc[i][j], a[i][0], a[i][1], a[i][2], a[i][3], b[j][0], b[j][1]);
        }
        if (kt + 1 < NT) {
            int nb = buf ^ 1;
            *(uint4*)&As[nb][r0][c0] = la;
            *(uint4*)&As[nb][r1][c0] = la1;
            *(uint4*)&Bs[nb][r0][c0] = lb;
            *(uint4*)&Bs[nb][r1][c0] = lb1;
            __syncthreads();
            buf = nb;
        }
    }

#pragma unroll
    for (int i = 0; i < 4; i++) {
        int r = row0 + m0w + i * 16 + (lane >> 2);
#pragma unroll
        for (int j = 0; j < 4; j++) {
            int c = col0 + n0w + j * 8 + ((lane & 3) << 1);
            *(float2*)&C[(size_t)r * N + c]       = make_float2(acc[i][j][0], acc[i][j][1]);
            *(float2*)&C[(size_t)(r + 8) * N + c] = make_float2(acc[i][j][2], acc[i][j][3]);
        }
    }
}

// ---------------- fp32 -> fp16 convert ----------------
__global__ void cvt_half(const float* __restrict__ in, __half* __restrict__ out, int n4)
{
    int i = blockIdx.x * blockDim.x + threadIdx.x;
    if (i >= n4) return;
    float4 v = ((const float4*)in)[i];
    union { __half h[4]; uint2 u; } p;
    p.h[0] = __float2half_rn(v.x); p.h[1] = __float2half_rn(v.y);
    p.h[2] = __float2half_rn(v.z); p.h[3] = __float2half_rn(v.w);
    ((uint2*)out)[i] = p.u;
}

__global__ void zero_kernel(float* p, int n)
{
    int i = blockIdx.x * blockDim.x + threadIdx.x;
    if (i < n) p[i] = 0.f;
}

// ---------------- fp32 split-K GEMM for b|a:  C[M,64] += A[M,K] * B[64,K]^T ----------------
__global__ void sgemm_ba(const float* __restrict__ A, const float* __restrict__ Wb,
                         const float* __restrict__ Wa, float* __restrict__ C, int M, int K)
{
    __shared__ float As[16][128];
    __shared__ float Bs[16][64];
    int tid = threadIdx.x;
    int tx = tid & 15, ty = tid >> 4;
    int row0 = blockIdx.y * 128;
    int kBeg = blockIdx.z * (K / 8), kEnd = kBeg + K / 8;

    float acc[8][4];
#pragma unroll
    for (int m = 0; m < 8; m++)
#pragma unroll
        for (int n = 0; n < 4; n++) acc[m][n] = 0.f;

    for (int kt = kBeg; kt < kEnd; kt += 16) {
#pragma unroll
        for (int i = 0; i < 2; i++) {
            int f = tid + i * 256;
            int r = f >> 2, c4 = (f & 3) << 2;
            float4 av = *(const float4*)(A + (size_t)(row0 + r) * K + kt + c4);
            As[c4][r] = av.x; As[c4+1][r] = av.y; As[c4+2][r] = av.z; As[c4+3][r] = av.w;
        }
        if (tid < 256) {
            int r = tid >> 2, c4 = (tid & 3) << 2;
            if (r < 64) {
                const float* src = (r < 32) ? (Wb + (size_t)r * K) : (Wa + (size_t)(r - 32) * K);
                float4 bv = *(const float4*)(src + kt + c4);
                Bs[c4][r] = bv.x; Bs[c4+1][r] = bv.y; Bs[c4+2][r] = bv.z; Bs[c4+3][r] = bv.w;
            }
        }
        __syncthreads();
#pragma unroll
        for (int k = 0; k < 16; k++) {
            float ra[8], rb[4];
            *(float4*)&ra[0] = *(float4*)&As[k][ty * 8];
            *(float4*)&ra[4] = *(float4*)&As[k][ty * 8 + 4];
            *(float4*)&rb[0] = *(float4*)&Bs[k][tx * 4];
#pragma unroll
            for (int m = 0; m < 8; m++)
#pragma unroll
                for (int n = 0; n < 4; n++) acc[m][n] += ra[m] * rb[n];
        }
        __syncthreads();
    }
#pragma unroll
    for (int m = 0; m < 8; m++) {
        int gr = row0 + ty * 8 + m;
#pragma unroll
        for (int n = 0; n < 4; n++)
            atomicAdd(&C[(size_t)gr * 64 + tx * 4 + n], acc[m][n]);
    }
}

// ---------------- beta / g finalize ----------------
__global__ void betag_kernel(const float* __restrict__ dt_bias, const float* __restrict__ A_log)
{
    int i = blockIdx.x * blockDim.x + threadIdx.x;
    if (i >= BT_ * NV_) return;
    int bt = i >> 5, h = i & 31;
    float braw = g_ba[bt * 64 + h];
    float araw = g_ba[bt * 64 + 32 + h];
    g_beta[i] = 1.f / (1.f + expf(-braw));
    float a = araw + dt_bias[h];
    float sp = (a > 20.f) ? a : log1pf(expf(a));
    g_gg[i] = -expf(A_log[h]) * sp;
}

// ---------------- causal depthwise conv(K=4) + silu + q/k L2 norm ----------------
__global__ void conv_kernel(const float* __restrict__ conv_w,
                            const float* __restrict__ conv_state,
                            const int* __restrict__ input_pos)
{
    __shared__ float srow[4096];
    int bt = blockIdx.x;
    int b = bt / T_, t = bt % T_;
    int tid = threadIdx.x;
    float keep = (input_pos[0] == 0) ? 0.f : 1.f;

    for (int d = tid; d < CONV_DIM_; d += 256) {
        float4 w = *(const float4*)(conv_w + (long)d * 4);
        float acc = 0.f;
#pragma unroll
        for (int j = 0; j < 4; j++) {
            int tt = t - 3 + j;
            float xv;
            if (tt >= 0) xv = g_qkv[(long)(b * T_ + tt) * CONV_DIM_ + d];
            else         xv = keep * conv_state[((long)b * CONV_DIM_ + d) * 4 + (t + 1 + j)];
            float wj = (j == 0) ? w.x : (j == 1) ? w.y : (j == 2) ? w.z : w.w;
            acc += wj * xv;
        }
        float s = acc / (1.f + expf(-acc));
        if (d < 4096) srow[d] = s;
        else          g_v[(long)bt * VAL_DIM_ + (d - 4096)] = s;
    }
    __syncthreads();

    int lane = tid & 31, warp = tid >> 5;
    for (int s = warp; s < 32; s += 8) {
        float vals[4]; float ss = 0.f;
#pragma unroll
        for (int j = 0; j < 4; j++) { vals[j] = srow[s * 128 + lane + 32 * j]; ss += vals[j] * vals[j]; }
#pragma unroll
        for (int off = 16; off; off >>= 1) ss += __shfl_xor_sync(0xffffffffu, ss, off);
        float inv = 1.f / fmaxf(sqrtf(ss), 1e-12f);
        float* dst = (s < 16) ? (g_q + (long)bt * KEY_DIM_ + s * 128)
                              : (g_k + (long)bt * KEY_DIM_ + (s - 16) * 128);
#pragma unroll
        for (int j = 0; j < 4; j++) dst[lane + 32 * j] = vals[j] * inv;
    }
}

// ---------------- chunked gated linear-attention recurrence ----------------
__device__ __forceinline__ void fma4(float4& a, float s, const float4 b)
{ a.x += s * b.x; a.y += s * b.y; a.z += s * b.z; a.w += s * b.w; }

__global__ void recur_kernel(const float* __restrict__ rstate, const int* __restrict__ input_pos)
{
    extern __shared__ float sm[];
    float* sq = sm;
    float* sk = sq + 64 * 132;
    float* sv = sk + 64 * 132;
    float* sA = sv + 64 * 68;
    float* sS = sA + 64 * 68;
    float* sG = sS + 128 * 68;
    float* sB = sG + 64;
    float* sW = sB + 64;

    int bidx = blockIdx.x;
    int vs = bidx & 1;
    int h  = (bidx >> 1) & (NV_ - 1);
    int b  = bidx >> 6;
    int hk = h >> 1;
    int tid = threadIdx.x;
    int tx = tid & 15, ty = tid >> 4;
    float keep = (input_pos[0] == 0) ? 0.f : 1.f;

#pragma unroll
    for (int j = 0; j < 8; j++) {
        int kk = ty * 8 + j;
        float4 v4 = *(const float4*)(rstate + (((long)(b * NV_ + h)) * DK_ + kk) * DV_ + vs * DVS + tx * 4);
        v4.x *= keep; v4.y *= keep; v4.z *= keep; v4.w *= keep;
        *(float4*)&sS[kk * 68 + tx * 4] = v4;
    }

    for (int ch = 0; ch < NCH; ch++) {
        int t0 = ch * LCH;
        __syncthreads();
        for (int f = tid; f < 64 * 32; f += 256) {
            int r = f >> 5, c = (f & 31) * 4;
            *(float4*)&sq[r * 132 + c] = *(const float4*)(g_q + (long)(b * T_ + t0 + r) * KEY_DIM_ + hk * DK_ + c);
            *(float4*)&sk[r * 132 + c] = *(const float4*)(g_k + (long)(b * T_ + t0 + r) * KEY_DIM_ + hk * DK_ + c);
        }
        for (int f = tid; f < 64 * 16; f += 256) {
            int r = f >> 4, c = (f & 15) * 4;
            *(float4*)&sv[r * 68 + c] = *(const float4*)(g_v + (long)(b * T_ + t0 + r) * VAL_DIM_ + h * DV_ + vs * DVS + c);
        }
        if (tid < 64) {
            sB[tid] = g_beta[(b * T_ + t0 + tid) * NV_ + h];
            sG[tid] = g_gg  [(b * T_ + t0 + tid) * NV_ + h];
        }
        __syncthreads();
        if (tid == 0) {
            float run = 0.f;
            for (int i = 0; i < LCH; i++) { run += sG[i]; sG[i] = run; }
        }
        __syncthreads();
        if (tid < 64) sW[tid] = expf(sG[63] - sG[tid]) * sB[tid];

        float accA[4][4];
#pragma unroll
        for (int a = 0; a < 4; a++)
#pragma unroll
            for (int c = 0; c < 4; c++) accA[a][c] = 0.f;
        for (int k4 = 0; k4 < DK_; k4 += 4) {
            float4 kb[4];
#pragma unroll
            for (int c = 0; c < 4; c++) kb[c] = *(float4*)&sk[(tx * 4 + c) * 132 + k4];
#pragma unroll
            for (int a = 0; a < 4; a++) {
                float4 qa = *(float4*)&sq[(ty * 4 + a) * 132 + k4];
#pragma unroll
                for (int c = 0; c < 4; c++)
                    accA[a][c] += qa.x * kb[c].x + qa.y * kb[c].y + qa.z * kb[c].z + qa.w * kb[c].w;
            }
        }
#pragma unroll
        for (int a = 0; a < 4; a++) {
            int t = ty * 4 + a; float gt = sG[t];
#pragma unroll
            for (int c = 0; c < 4; c++) {
                int i = tx * 4 + c;
                sA[t * 68 + i] = (i <= t) ? accA[a][c] * expf(gt - sG[i]) * sB[i] : 0.f;
            }
        }
        __syncthreads();

        float4 acc[4], acci[4];
#pragma unroll
        for (int a = 0; a < 4; a++) { acc[a] = make_float4(0,0,0,0); acci[a] = make_float4(0,0,0,0); }
        for (int i4 = 0; i4 < LCH; i4 += 4) {
            float4 vv[4];
#pragma unroll
            for (int ii = 0; ii < 4; ii++) vv[ii] = *(float4*)&sv[(i4 + ii) * 68 + tx * 4];
#pragma unroll
            for (int a = 0; a < 4; a++) {
                float4 av = *(float4*)&sA[(ty * 4 + a) * 68 + i4];
                fma4(acc[a], av.x, vv[0]); fma4(acc[a], av.y, vv[1]);
                fma4(acc[a], av.z, vv[2]); fma4(acc[a], av.w, vv[3]);
            }
        }
        for (int k4 = 0; k4 < DK_; k4 += 4) {
            float4 ssr[4];
#pragma unroll
            for (int kk = 0; kk < 4; kk++) ssr[kk] = *(float4*)&sS[(k4 + kk) * 68 + tx * 4];
#pragma unroll
            for (int a = 0; a < 4; a++) {
                float4 qa = *(float4*)&sq[(ty * 4 + a) * 132 + k4];
                fma4(acci[a], qa.x, ssr[0]); fma4(acci[a], qa.y, ssr[1]);
                fma4(acci[a], qa.z, ssr[2]); fma4(acci[a], qa.w, ssr[3]);
            }
        }
#pragma unroll
        for (int a = 0; a < 4; a++) {
            int t = ty * 4 + a;
            float et = expf(sG[t]);
            float4 w4 = make_float4(acc[a].x + et * acci[a].x, acc[a].y + et * acci[a].y,
                                    acc[a].z + et * acci[a].z, acc[a].w + et * acci[a].w);
            *(float4*)(g_o + (long)(b * T_ + t0 + t) * VAL_DIM_ + h * DV_ + vs * DVS + tx * 4) = w4;
        }
        __syncthreads();

        float elast = expf(sG[63]);
        float4 Sreg[8];
#pragma unroll
        for (int j = 0; j < 8; j++) {
            Sreg[j] = *(float4*)&sS[(ty * 8 + j) * 68 + tx * 4];
            Sreg[j].x *= elast; Sreg[j].y *= elast; Sreg[j].z *= elast; Sreg[j].w *= elast;
        }
        for (int i = 0; i < LCH; i++) {
            float w = sW[i];
            float4 vv = *(float4*)&sv[i * 68 + tx * 4];
            float4 k0 = *(float4*)&sk[i * 132 + ty * 8];
            float4 k1 = *(float4*)&sk[i * 132 + ty * 8 + 4];
            fma4(Sreg[0], w * k0.x, vv); fma4(Sreg[1], w * k0.y, vv);
            fma4(Sreg[2], w * k0.z, vv); fma4(Sreg[3], w * k0.w, vv);
            fma4(Sreg[4], w * k1.x, vv); fma4(Sreg[5], w * k1.y, vv);
            fma4(Sreg[6], w * k1.z, vv); fma4(Sreg[7], w * k1.w, vv);
        }
#pragma unroll
        for (int j = 0; j < 8; j++)
            *(float4*)&sS[(ty * 8 + j) * 68 + tx * 4] = Sreg[j];
    }
}

// ---------------- gated RMSNorm -> fp16 ----------------
__global__ void rmsnorm_kernel(const float* __restrict__ norm_w)
{
    int bh = blockIdx.x;
    int bt = bh >> 5, h = bh & 31;
    int tid = threadIdx.x;
    long idx = (long)bt * VAL_DIM_ + h * DV_ + tid;
    float o = g_o[idx];
    float z = g_z[idx];
    float val = o * (z / (1.f + expf(-z)));
    float s = val * val;
#pragma unroll
    for (int off = 16; off; off >>= 1) s += __shfl_xor_sync(0xffffffffu, s, off);
    __shared__ float red[4];
    int warp = tid >> 5, lane = tid & 31;
    if (lane == 0) red[warp] = s;
    __syncthreads();
    float tot = red[0] + red[1] + red[2] + red[3];
    float scale = rsqrtf(tot * (1.f / 128.f) + 1e-6f) * norm_w[tid];
    g_oh[idx] = __float2half_rn(val * scale);
}

// ---------------- launch (fork-join multi-stream, graph-capturable) ----------------
extern "C" void kernel_launch(void* const* d_in, const int* in_sizes, int n_in,
                              void* d_out, int out_size)
{
    const float* x          = (const float*)d_in[0];
    const int*   input_pos  = (const int*)  d_in[1];
    const float* W_qkv      = (const float*)d_in[2];
    const float* W_z        = (const float*)d_in[3];
    const float* W_b        = (const float*)d_in[4];
    const float* W_a        = (const float*)d_in[5];
    const float* conv_w     = (const float*)d_in[6];
    const float* dt_bias    = (const float*)d_in[7];
    const float* A_log      = (const float*)d_in[8];
    const float* norm_w     = (const float*)d_in[9];
    const float* W_out      = (const float*)d_in[10];
    const float* conv_state = (const float*)d_in[11];
    const float* rstate     = (const float*)d_in[12];
    float* out = (float*)d_out;

    float *p_qkv, *p_z, *p_ba;
    __half *p_xh, *p_Wqh, *p_Wzh, *p_Woh, *p_oh;
    cudaGetSymbolAddress((void**)&p_qkv, g_qkv);
    cudaGetSymbolAddress((void**)&p_z,   g_z);
    cudaGetSymbolAddress((void**)&p_ba,  g_ba);
    cudaGetSymbolAddress((void**)&p_xh,  g_xh);
    cudaGetSymbolAddress((void**)&p_Wqh, g_Wqh);
    cudaGetSymbolAddress((void**)&p_Wzh, g_Wzh);
    cudaGetSymbolAddress((void**)&p_Woh, g_Woh);
    cudaGetSymbolAddress((void**)&p_oh,  g_oh);

    const int RECUR_SMEM = (64*132*2 + 64*68*2 + 128*68 + 64*3) * 4;
    cudaFuncSetAttribute(recur_kernel, cudaFuncAttributeMaxDynamicSharedMemorySize, RECUR_SMEM);

    // side streams + events, created once (outside capture, on the first correctness call)
    static cudaStream_t sZ = nullptr, sBA = nullptr, sWo = nullptr;
    static cudaEvent_t evRoot, evX, evZ, evBA, evWo;
    if (!sZ) {
        cudaStreamCreateWithFlags(&sZ,  cudaStreamNonBlocking);
        cudaStreamCreateWithFlags(&sBA, cudaStreamNonBlocking);
        cudaStreamCreateWithFlags(&sWo, cudaStreamNonBlocking);
        cudaEventCreateWithFlags(&evRoot, cudaEventDisableTiming);
        cudaEventCreateWithFlags(&evX,    cudaEventDisableTiming);
        cudaEventCreateWithFlags(&evZ,    cudaEventDisableTiming);
        cudaEventCreateWithFlags(&evBA,   cudaEventDisableTiming);
        cudaEventCreateWithFlags(&evWo,   cudaEventDisableTiming);
    }

    // ---- fork ----
    cudaEventRecord(evRoot, 0);
    cudaStreamWaitEvent(sZ,  evRoot, 0);
    cudaStreamWaitEvent(sBA, evRoot, 0);
    cudaStreamWaitEvent(sWo, evRoot, 0);

    // main stream: x cvt -> qkv GEMM -> conv -> recur -> rmsnorm -> out GEMM
    cvt_half<<<(BT_*C_/4 + 255)/256, 256>>>(x, p_xh, BT_*C_/4);
    cudaEventRecord(evX, 0);
    cvt_half<<<(CONV_DIM_*C_/4 + 255)/256, 256>>>(W_qkv, p_Wqh, CONV_DIM_*C_/4);
    hgemm_nt<<<dim3(CONV_DIM_/128, BT_/128), 256>>>(p_xh, p_Wqh, p_qkv, BT_, CONV_DIM_, C_);
    conv_kernel<<<BT_, 256>>>(conv_w, conv_state, input_pos);

    // z branch: Wz cvt (indep) then z GEMM (needs x fp16)
    cvt_half<<<(VAL_DIM_*C_/4 + 255)/256, 256, 0, sZ>>>(W_z, p_Wzh, VAL_DIM_*C_/4);
    cudaStreamWaitEvent(sZ, evX, 0);
    hgemm_nt<<<dim3(VAL_DIM_/128, BT_/128), 256, 0, sZ>>>(p_xh, p_Wzh, p_z, BT_, VAL_DIM_, C_);
    cudaEventRecord(evZ, sZ);

    // b/a branch: fp32 split-K GEMM off raw x, then finalize beta/g
    zero_kernel<<<(BT_*64 + 255)/256, 256, 0, sBA>>>(p_ba, BT_*64);
    sgemm_ba<<<dim3(1, BT_/128, 8), 256, 0, sBA>>>(x, W_b, W_a, p_ba, BT_, C_);
    betag_kernel<<<(BT_ * NV_ + 255) / 256, 256, 0, sBA>>>(dt_bias, A_log);
    cudaEventRecord(evBA, sBA);

    // Wo branch: convert out-proj weights
    cvt_half<<<(C_*VAL_DIM_/4 + 255)/256, 256, 0, sWo>>>(W_out, p_Woh, C_*VAL_DIM_/4);
    cudaEventRecord(evWo, sWo);

    // join: recur needs conv (main) + beta/g
    cudaStreamWaitEvent(0, evBA, 0);
    recur_kernel<<<B_ * NV_ * SPLITV, 256, RECUR_SMEM>>>(rstate, input_pos);

    // rmsnorm needs recur (main) + z
    cudaStreamWaitEvent(0, evZ, 0);
    rmsnorm_kernel<<<BT_ * NV_, 128>>>(norm_w);

    // out GEMM needs rmsnorm (main) + Wo fp16
    cudaStreamWaitEvent(0, evWo, 0);
    hgemm_nt<<<dim3(C_/128, BT_/128), 256>>>(p_oh, p_Woh, out, BT_, C_, VAL_DIM_);
}

// round 5
// speedup vs baseline: 4.8598x; 1.1508x over previous
#include <cuda_runtime.h>
#include <cuda_fp16.h>
#include <math.h>
#include <stdint.h>

#define B_ 2
#define T_ 2048
#define C_ 2048
#define NV_ 32
#define NHK_ 16
#define DK_ 128
#define DV_ 128
#define KEY_DIM_ 2048
#define VAL_DIM_ 4096
#define CONV_DIM_ 8192
#define BT_ (B_*T_)
#define LCH 64
#define NCH (T_/LCH)
#define SPLITV 2
#define DVS (DV_/SPLITV)

// ---------------- scratch (static device globals; no allocation) ----------------
__device__ float g_qkv [BT_*CONV_DIM_];
__device__ float g_z   [BT_*VAL_DIM_];
__device__ float g_q   [BT_*KEY_DIM_];
__device__ float g_k   [BT_*KEY_DIM_];
__device__ float g_v   [BT_*VAL_DIM_];
__device__ float g_ba  [BT_*64];
__device__ float g_beta[BT_*NV_];
__device__ float g_gg  [BT_*NV_];
__device__ float g_o   [BT_*VAL_DIM_];
__device__ float g_qk  [(size_t)B_*NHK_*NCH*LCH*LCH];   // raw q.k scores per (b,hk,chunk)

__device__ __half g_xh [BT_*C_];
__device__ __half g_Wqh[CONV_DIM_*C_];
__device__ __half g_Wzh[VAL_DIM_*C_];
__device__ __half g_Woh[C_*VAL_DIM_];
__device__ __half g_oh [BT_*VAL_DIM_];

// ---------------- helpers ----------------
__device__ __forceinline__ uint32_t smem_u32(const void* p) {
    uint32_t a;
    asm("{ .reg .u64 t; cvta.to.shared.u64 t, %1; cvt.u32.u64 %0, t; }" : "=r"(a) : "l"(p));
    return a;
}
__device__ __forceinline__ void ldsm_x4(uint32_t& r0, uint32_t& r1, uint32_t& r2, uint32_t& r3, uint32_t addr) {
    asm volatile("ldmatrix.sync.aligned.m8n8.x4.shared.b16 {%0,%1,%2,%3}, [%4];"
                 : "=r"(r0), "=r"(r1), "=r"(r2), "=r"(r3) : "r"(addr));
}
__device__ __forceinline__ void mma16816(float* c, uint32_t a0, uint32_t a1, uint32_t a2, uint32_t a3,
                                         uint32_t b0, uint32_t b1) {
    asm volatile("mma.sync.aligned.m16n8k16.row.col.f32.f16.f16.f32 "
                 "{%0,%1,%2,%3}, {%4,%5,%6,%7}, {%8,%9}, {%0,%1,%2,%3};"
                 : "+f"(c[0]), "+f"(c[1]), "+f"(c[2]), "+f"(c[3])
                 : "r"(a0), "r"(a1), "r"(a2), "r"(a3), "r"(b0), "r"(b1));
}
#define CP_ASYNC16(dst, src) asm volatile("cp.async.cg.shared.global [%0], [%1], 16;" :: "r"(dst), "l"(src))
#define CP_COMMIT()          asm volatile("cp.async.commit_group;" ::: "memory")
#define CP_WAIT1()           asm volatile("cp.async.wait_group 1;" ::: "memory")

// ---------------- fp16 HGEMM: C[M,N] = A[M,K] * B[N,K]^T, 3-stage cp.async ----------------
__global__ __launch_bounds__(256, 2)
void hgemm_nt(const __half* __restrict__ A, const __half* __restrict__ Bm,
              float* __restrict__ C, int M, int N, int K)
{
    extern __shared__ __half hsm[];
    const int STG = 128 * 40;                  // halfs per stage per operand
    __half* AsP = hsm;
    __half* BsP = hsm + 3 * STG;

    int tid = threadIdx.x;
    int lane = tid & 31, wid = tid >> 5;
    int wm = wid & 1, wn = wid >> 1;
    int m0w = wm * 64, n0w = wn * 32;
    int row0 = blockIdx.y * 128, col0 = blockIdx.x * 128;

    uint32_t aBase = smem_u32(AsP);
    uint32_t bBase = smem_u32(BsP);

    float acc[4][4][4];
#pragma unroll
    for (int i = 0; i < 4; i++)
#pragma unroll
        for (int j = 0; j < 4; j++)
#pragma unroll
            for (int e = 0; e < 4; e++) acc[i][j][e] = 0.f;

    const int NT = K >> 5;
    int lr = tid >> 2, lc = (tid & 3) << 3;      // loader: rows 0..63 (+64), 8-half chunks
    int lr1 = lr + 64;

    // issue stage for k-tile kt into buffer s
    auto issue = [&](int kt, int s) {
        int k0 = kt << 5;
        uint32_t da0 = aBase + ((s * STG + lr  * 40 + lc) << 1);
        uint32_t da1 = aBase + ((s * STG + lr1 * 40 + lc) << 1);
        uint32_t db0 = bBase + ((s * STG + lr  * 40 + lc) << 1);
        uint32_t db1 = bBase + ((s * STG + lr1 * 40 + lc) << 1);
        CP_ASYNC16(da0, A  + (size_t)(row0 + lr ) * K + k0 + lc);
        CP_ASYNC16(da1, A  + (size_t)(row0 + lr1) * K + k0 + lc);
        CP_ASYNC16(db0, Bm + (size_t)(col0 + lr ) * K + k0 + lc);
        CP_ASYNC16(db1, Bm + (size_t)(col0 + lr1) * K + k0 + lc);
        CP_COMMIT();
    };

    issue(0, 0);
    issue(1, 1);

    for (int kt = 0; kt < NT; kt++) {
        CP_WAIT1();
        __syncthreads();
        if (kt + 2 < NT) issue(kt + 2, (kt + 2) % 3);
        int s = kt % 3;
#pragma unroll
        for (int kk = 0; kk < 32; kk += 16) {
            uint32_t a[4][4], b[4][2];
#pragma unroll
            for (int i = 0; i < 4; i++) {
                int r = m0w + i * 16 + (lane & 15);
                int c = kk + ((lane >> 4) << 3);
                ldsm_x4(a[i][0], a[i][1], a[i][2], a[i][3],
                        aBase + ((s * STG + r * 40 + c) << 1));
            }
#pragma unroll
            for (int j = 0; j < 2; j++) {
                int q = lane >> 3, rr = lane & 7;
                int r = n0w + j * 16 + ((q >> 1) << 3) + rr;
                int c = kk + ((q & 1) << 3);
                uint32_t t0, t1, t2, t3;
                ldsm_x4(t0, t1, t2, t3, bBase + ((s * STG + r * 40 + c) << 1));
                b[2*j][0] = t0; b[2*j][1] = t1; b[2*j+1][0] = t2; b[2*j+1][1] = t3;
            }
#pragma unroll
            for (int i = 0; i < 4; i++)
#pragma unroll
                for (int j = 0; j < 4; j++)
                    mma16816(acc[i][j], a[i][0], a[i][1], a[i][2], a[i][3], b[j][0], b[j][1]);
        }
        __syncthreads();
    }

#pragma unroll
    for (int i = 0; i < 4; i++) {
        int r = row0 + m0w + i * 16 + (lane >> 2);
#pragma unroll
        for (int j = 0; j < 4; j++) {
            int c = col0 + n0w + j * 8 + ((lane & 3) << 1);
            *(float2*)&C[(size_t)r * N + c]       = make_float2(acc[i][j][0], acc[i][j][1]);
            *(float2*)&C[(size_t)(r + 8) * N + c] = make_float2(acc[i][j][2], acc[i][j][3]);
        }
    }
}

// ---------------- fp32 -> fp16 convert ----------------
__global__ void cvt_half(const float* __restrict__ in, __half* __restrict__ out, int n4)
{
    int i = blockIdx.x * blockDim.x + threadIdx.x;
    if (i >= n4) return;
    float4 v = ((const float4*)in)[i];
    union { __half h[4]; uint2 u; } p;
    p.h[0] = __float2half_rn(v.x); p.h[1] = __float2half_rn(v.y);
    p.h[2] = __float2half_rn(v.z); p.h[3] = __float2half_rn(v.w);
    ((uint2*)out)[i] = p.u;
}

__global__ void zero_kernel(float* p, int n)
{
    int i = blockIdx.x * blockDim.x + threadIdx.x;
    if (i < n) p[i] = 0.f;
}

// ---------------- fp32 split-K GEMM for b|a ----------------
__global__ void sgemm_ba(const float* __restrict__ A, const float* __restrict__ Wb,
                         const float* __restrict__ Wa, float* __restrict__ C, int M, int K)
{
    __shared__ float As[16][128];
    __shared__ float Bs[16][64];
    int tid = threadIdx.x;
    int tx = tid & 15, ty = tid >> 4;
    int row0 = blockIdx.y * 128;
    int kBeg = blockIdx.z * (K / 8), kEnd = kBeg + K / 8;

    float acc[8][4];
#pragma unroll
    for (int m = 0; m < 8; m++)
#pragma unroll
        for (int n = 0; n < 4; n++) acc[m][n] = 0.f;

    for (int kt = kBeg; kt < kEnd; kt += 16) {
#pragma unroll
        for (int i = 0; i < 2; i++) {
            int f = tid + i * 256;
            int r = f >> 2, c4 = (f & 3) << 2;
            float4 av = *(const float4*)(A + (size_t)(row0 + r) * K + kt + c4);
            As[c4][r] = av.x; As[c4+1][r] = av.y; As[c4+2][r] = av.z; As[c4+3][r] = av.w;
        }
        {
            int r = tid >> 2, c4 = (tid & 3) << 2;
            if (r < 64) {
                const float* src = (r < 32) ? (Wb + (size_t)r * K) : (Wa + (size_t)(r - 32) * K);
                float4 bv = *(const float4*)(src + kt + c4);
                Bs[c4][r] = bv.x; Bs[c4+1][r] = bv.y; Bs[c4+2][r] = bv.z; Bs[c4+3][r] = bv.w;
            }
        }
        __syncthreads();
#pragma unroll
        for (int k = 0; k < 16; k++) {
            float ra[8], rb[4];
            *(float4*)&ra[0] = *(float4*)&As[k][ty * 8];
            *(float4*)&ra[4] = *(float4*)&As[k][ty * 8 + 4];
            *(float4*)&rb[0] = *(float4*)&Bs[k][tx * 4];
#pragma unroll
            for (int m = 0; m < 8; m++)
#pragma unroll
                for (int n = 0; n < 4; n++) acc[m][n] += ra[m] * rb[n];
        }
        __syncthreads();
    }
#pragma unroll
    for (int m = 0; m < 8; m++) {
        int gr = row0 + ty * 8 + m;
#pragma unroll
        for (int n = 0; n < 4; n++)
            atomicAdd(&C[(size_t)gr * 64 + tx * 4 + n], acc[m][n]);
    }
}

// ---------------- beta / g finalize ----------------
__global__ void betag_kernel(const float* __restrict__ dt_bias, const float* __restrict__ A_log)
{
    int i = blockIdx.x * blockDim.x + threadIdx.x;
    if (i >= BT_ * NV_) return;
    int bt = i >> 5, h = i & 31;
    float braw = g_ba[bt * 64 + h];
    float araw = g_ba[bt * 64 + 32 + h];
    g_beta[i] = 1.f / (1.f + expf(-braw));
    float a = araw + dt_bias[h];
    float sp = (a > 20.f) ? a : log1pf(expf(a));
    g_gg[i] = -expf(A_log[h]) * sp;
}

// ---------------- causal depthwise conv(K=4) + silu + q/k L2 norm ----------------
__global__ void conv_kernel(const float* __restrict__ conv_w,
                            const float* __restrict__ conv_state,
                            const int* __restrict__ input_pos)
{
    __shared__ float srow[4096];
    int bt = blockIdx.x;
    int b = bt / T_, t = bt % T_;
    int tid = threadIdx.x;
    float keep = (input_pos[0] == 0) ? 0.f : 1.f;

    for (int d = tid; d < CONV_DIM_; d += 256) {
        float4 w = *(const float4*)(conv_w + (long)d * 4);
        float acc = 0.f;
#pragma unroll
        for (int j = 0; j < 4; j++) {
            int tt = t - 3 + j;
            float xv;
            if (tt >= 0) xv = g_qkv[(long)(b * T_ + tt) * CONV_DIM_ + d];
            else         xv = keep * conv_state[((long)b * CONV_DIM_ + d) * 4 + (t + 1 + j)];
            float wj = (j == 0) ? w.x : (j == 1) ? w.y : (j == 2) ? w.z : w.w;
            acc += wj * xv;
        }
        float s = acc / (1.f + expf(-acc));
        if (d < 4096) srow[d] = s;
        else          g_v[(long)bt * VAL_DIM_ + (d - 4096)] = s;
    }
    __syncthreads();

    int lane = tid & 31, warp = tid >> 5;
    for (int s = warp; s < 32; s += 8) {
        float vals[4]; float ss = 0.f;
#pragma unroll
        for (int j = 0; j < 4; j++) { vals[j] = srow[s * 128 + lane + 32 * j]; ss += vals[j] * vals[j]; }
#pragma unroll
        for (int off = 16; off; off >>= 1) ss += __shfl_xor_sync(0xffffffffu, ss, off);
        float inv = 1.f / fmaxf(sqrtf(ss), 1e-12f);
        float* dst = (s < 16) ? (g_q + (long)bt * KEY_DIM_ + s * 128)
                              : (g_k + (long)bt * KEY_DIM_ + (s - 16) * 128);
#pragma unroll
        for (int j = 0; j < 4; j++) dst[lane + 32 * j] = vals[j] * inv;
    }
}

// ---------------- QK precompute: raw scores q_t . k_i per (b,hk,chunk) ----------------
__global__ __launch_bounds__(256)
void qk_kernel()
{
    extern __shared__ float qsm[];
    float* sq = qsm;                 // 64*132
    float* sk = qsm + 64 * 132;      // 64*132

    int bidx = blockIdx.x;           // b*NHK_*NCH + hk*NCH + ch
    int ch = bidx % NCH;
    int hk = (bidx / NCH) % NHK_;
    int b  = bidx / (NCH * NHK_);
    int t0 = ch * LCH;
    int tid = threadIdx.x;
    int tx = tid & 15, ty = tid >> 4;

    for (int f = tid; f < 64 * 32; f += 256) {
        int r = f >> 5, c = (f & 31) * 4;
        *(float4*)&sq[r * 132 + c] = *(const float4*)(g_q + (size_t)(b * T_ + t0 + r) * KEY_DIM_ + hk * DK_ + c);
        *(float4*)&sk[r * 132 + c] = *(const float4*)(g_k + (size_t)(b * T_ + t0 + r) * KEY_DIM_ + hk * DK_ + c);
    }
    __syncthreads();

    float accA[4][4];
#pragma unroll
    for (int a = 0; a < 4; a++)
#pragma unroll
        for (int c = 0; c < 4; c++) accA[a][c] = 0.f;

    // causal tile skip: tile rows t = ty*4.., cols i = tx*4..; skip if min i > max t
    if (tx * 4 <= ty * 4 + 3) {
        for (int k4 = 0; k4 < DK_; k4 += 4) {
            float4 kb[4];
#pragma unroll
            for (int c = 0; c < 4; c++) kb[c] = *(float4*)&sk[(tx * 4 + c) * 132 + k4];
#pragma unroll
            for (int a = 0; a < 4; a++) {
                float4 qa = *(float4*)&sq[(ty * 4 + a) * 132 + k4];
#pragma unroll
                for (int c = 0; c < 4; c++)
                    accA[a][c] += qa.x * kb[c].x + qa.y * kb[c].y + qa.z * kb[c].z + qa.w * kb[c].w;
            }
        }
    }
    float* dst = g_qk + (size_t)bidx * (LCH * LCH);
#pragma unroll
    for (int a = 0; a < 4; a++) {
        float4 w = make_float4(accA[a][0], accA[a][1], accA[a][2], accA[a][3]);
        *(float4*)&dst[(ty * 4 + a) * 64 + tx * 4] = w;
    }
}

// ---------------- chunked gated linear-attention recurrence (512 threads) ----------------
__device__ __forceinline__ void fma4(float4& a, float s, const float4 b)
{ a.x += s * b.x; a.y += s * b.y; a.z += s * b.z; a.w += s * b.w; }

__global__ __launch_bounds__(512)
void recur_kernel(const float* __restrict__ rstate, const int* __restrict__ input_pos)
{
    extern __shared__ float sm[];
    float* sq = sm;                  // 64*132
    float* sk = sq + 64 * 132;       // 64*132
    float* sv = sk + 64 * 132;       // 64*68
    float* sA = sv + 64 * 68;        // 64*68
    float* sS = sA + 64 * 68;        // 128*68
    float* sG = sS + 128 * 68;       // 64
    float* sB = sG + 64;             // 64
    float* sW = sB + 64;             // 64

    int bidx = blockIdx.x;
    int vs = bidx & 1;
    int h  = (bidx >> 1) & (NV_ - 1);
    int b  = bidx >> 6;
    int hk = h >> 1;
    int tid = threadIdx.x;
    int tx = tid & 15, ty = tid >> 4;      // tx: 16 col groups, ty: 0..31
    float keep = (input_pos[0] == 0) ? 0.f : 1.f;

    // state rows ty*4..+3, cols tx*4..+3
#pragma unroll
    for (int j = 0; j < 4; j++) {
        int kk = ty * 4 + j;
        float4 v4 = *(const float4*)(rstate + (((size_t)(b * NV_ + h)) * DK_ + kk) * DV_ + vs * DVS + tx * 4);
        v4.x *= keep; v4.y *= keep; v4.z *= keep; v4.w *= keep;
        *(float4*)&sS[kk * 68 + tx * 4] = v4;
    }

    const float* qkBase = g_qk + ((size_t)(b * NHK_ + hk) * NCH) * (LCH * LCH);

    for (int ch = 0; ch < NCH; ch++) {
        int t0 = ch * LCH;
        __syncthreads();
        for (int f = tid; f < 64 * 32; f += 512) {
            int r = f >> 5, c = (f & 31) * 4;
            *(float4*)&sq[r * 132 + c] = *(const float4*)(g_q + (size_t)(b * T_ + t0 + r) * KEY_DIM_ + hk * DK_ + c);
            *(float4*)&sk[r * 132 + c] = *(const float4*)(g_k + (size_t)(b * T_ + t0 + r) * KEY_DIM_ + hk * DK_ + c);
        }
        for (int f = tid; f < 64 * 16; f += 512) {
            int r = f >> 4, c = (f & 15) * 4;
            *(float4*)&sv[r * 68 + c] = *(const float4*)(g_v + (size_t)(b * T_ + t0 + r) * VAL_DIM_ + h * DV_ + vs * DVS + c);
        }
        if (tid < 64) {
            sB[tid] = g_beta[(b * T_ + t0 + tid) * NV_ + h];
            sG[tid] = g_gg  [(b * T_ + t0 + tid) * NV_ + h];
        }
        __syncthreads();
        if (tid == 0) {
            float run = 0.f;
            for (int i = 0; i < LCH; i++) { run += sG[i]; sG[i] = run; }
        }
        __syncthreads();
        if (tid < 64) sW[tid] = expf(sG[63] - sG[tid]) * sB[tid];

        // sA[t][i] = QK[t][i] * exp(Gt - Gi) * beta_i, masked i<=t. 8 elems/thread.
        {
            const float* qkT = qkBase + (size_t)ch * (LCH * LCH);
            int f0 = tid * 8;
            int t = f0 >> 6, i0 = f0 & 63;
            float gt = sG[t];
            float4 qa = *(const float4*)(qkT + t * 64 + i0);
            float4 qb = *(const float4*)(qkT + t * 64 + i0 + 4);
            float r[8] = {qa.x, qa.y, qa.z, qa.w, qb.x, qb.y, qb.z, qb.w};
#pragma unroll
            for (int j = 0; j < 8; j++) {
                int i = i0 + j;
                r[j] = (i <= t) ? r[j] * expf(gt - sG[i]) * sB[i] : 0.f;
            }
            *(float4*)&sA[t * 68 + i0]     = make_float4(r[0], r[1], r[2], r[3]);
            *(float4*)&sA[t * 68 + i0 + 4] = make_float4(r[4], r[5], r[6], r[7]);
        }
        __syncthreads();

        // out rows ty*2, ty*2+1, cols tx*4
        float4 acc[2], acci[2];
#pragma unroll
        for (int a = 0; a < 2; a++) { acc[a] = make_float4(0,0,0,0); acci[a] = make_float4(0,0,0,0); }
        for (int i4 = 0; i4 < LCH; i4 += 4) {
            float4 vv[4];
#pragma unroll
            for (int ii = 0; ii < 4; ii++) vv[ii] = *(float4*)&sv[(i4 + ii) * 68 + tx * 4];
#pragma unroll
            for (int a = 0; a < 2; a++) {
                float4 av = *(float4*)&sA[(ty * 2 + a) * 68 + i4];
                fma4(acc[a], av.x, vv[0]); fma4(acc[a], av.y, vv[1]);
                fma4(acc[a], av.z, vv[2]); fma4(acc[a], av.w, vv[3]);
            }
        }
        for (int k4 = 0; k4 < DK_; k4 += 4) {
            float4 ssr[4];
#pragma unroll
            for (int kk = 0; kk < 4; kk++) ssr[kk] = *(float4*)&sS[(k4 + kk) * 68 + tx * 4];
#pragma unroll
            for (int a = 0; a < 2; a++) {
                float4 qa = *(float4*)&sq[(ty * 2 + a) * 132 + k4];
                fma4(acci[a], qa.x, ssr[0]); fma4(acci[a], qa.y, ssr[1]);
                fma4(acci[a], qa.z, ssr[2]); fma4(acci[a], qa.w, ssr[3]);
            }
        }
#pragma unroll
        for (int a = 0; a < 2; a++) {
            int t = ty * 2 + a;
            float et = expf(sG[t]);
            float4 w4 = make_float4(acc[a].x + et * acci[a].x, acc[a].y + et * acci[a].y,
                                    acc[a].z + et * acci[a].z, acc[a].w + et * acci[a].w);
            *(float4*)(g_o + (size_t)(b * T_ + t0 + t) * VAL_DIM_ + h * DV_ + vs * DVS + tx * 4) = w4;
        }
        __syncthreads();

        // S = exp(G_last)*S + sum_i w_i * k_i (outer) v_i ; rows ty*4..+3, cols tx*4
        float elast = expf(sG[63]);
        float4 Sreg[4];
#pragma unroll
        for (int j = 0; j < 4; j++) {
            Sreg[j] = *(float4*)&sS[(ty * 4 + j) * 68 + tx * 4];
            Sreg[j].x *= elast; Sreg[j].y *= elast; Sreg[j].z *= elast; Sreg[j].w *= elast;
        }
        for (int i = 0; i < LCH; i++) {
            float w = sW[i];
            float4 vv = *(float4*)&sv[i * 68 + tx * 4];
            float4 k0 = *(float4*)&sk[i * 132 + ty * 4];
            fma4(Sreg[0], w * k0.x, vv); fma4(Sreg[1], w * k0.y, vv);
            fma4(Sreg[2], w * k0.z, vv); fma4(Sreg[3], w * k0.w, vv);
        }
#pragma unroll
        for (int j = 0; j < 4; j++)
            *(float4*)&sS[(ty * 4 + j) * 68 + tx * 4] = Sreg[j];
    }
}

// ---------------- gated RMSNorm -> fp16 ----------------
__global__ void rmsnorm_kernel(const float* __restrict__ norm_w)
{
    int bh = blockIdx.x;
    int bt = bh >> 5, h = bh & 31;
    int tid = threadIdx.x;
    long idx = (long)bt * VAL_DIM_ + h * DV_ + tid;
    float o = g_o[idx];
    float z = g_z[idx];
    float val = o * (z / (1.f + expf(-z)));
    float s = val * val;
#pragma unroll
    for (int off = 16; off; off >>= 1) s += __shfl_xor_sync(0xffffffffu, s, off);
    __shared__ float red[4];
    int warp = tid >> 5, lane = tid & 31;
    if (lane == 0) red[warp] = s;
    __syncthreads();
    float tot = red[0] + red[1] + red[2] + red[3];
    float scale = rsqrtf(tot * (1.f / 128.f) + 1e-6f) * norm_w[tid];
    g_oh[idx] = __float2half_rn(val * scale);
}

// ---------------- launch (fork-join multi-stream, graph-capturable) ----------------
extern "C" void kernel_launch(void* const* d_in, const int* in_sizes, int n_in,
                              void* d_out, int out_size)
{
    const float* x          = (const float*)d_in[0];
    const int*   input_pos  = (const int*)  d_in[1];
    const float* W_qkv      = (const float*)d_in[2];
    const float* W_z        = (const float*)d_in[3];
    const float* W_b        = (const float*)d_in[4];
    const float* W_a        = (const float*)d_in[5];
    const float* conv_w     = (const float*)d_in[6];
    const float* dt_bias    = (const float*)d_in[7];
    const float* A_log      = (const float*)d_in[8];
    const float* norm_w     = (const float*)d_in[9];
    const float* W_out      = (const float*)d_in[10];
    const float* conv_state = (const float*)d_in[11];
    const float* rstate     = (const float*)d_in[12];
    float* out = (float*)d_out;

    float *p_qkv, *p_z, *p_ba;
    __half *p_xh, *p_Wqh, *p_Wzh, *p_Woh, *p_oh;
    cudaGetSymbolAddress((void**)&p_qkv, g_qkv);
    cudaGetSymbolAddress((void**)&p_z,   g_z);
    cudaGetSymbolAddress((void**)&p_ba,  g_ba);
    cudaGetSymbolAddress((void**)&p_xh,  g_xh);
    cudaGetSymbolAddress((void**)&p_Wqh, g_Wqh);
    cudaGetSymbolAddress((void**)&p_Wzh, g_Wzh);
    cudaGetSymbolAddress((void**)&p_Woh, g_Woh);
    cudaGetSymbolAddress((void**)&p_oh,  g_oh);

    const int RECUR_SMEM = (64*132*2 + 64*68*2 + 128*68 + 64*3) * 4;   // 137984 B
    const int QK_SMEM    = (64*132*2) * 4;                              // 67584 B
    const int HG_SMEM    = 6 * 128 * 40 * 2;                            // 61440 B
    cudaFuncSetAttribute(recur_kernel, cudaFuncAttributeMaxDynamicSharedMemorySize, RECUR_SMEM);
    cudaFuncSetAttribute(qk_kernel,    cudaFuncAttributeMaxDynamicSharedMemorySize, QK_SMEM);
    cudaFuncSetAttribute(hgemm_nt,     cudaFuncAttributeMaxDynamicSharedMemorySize, HG_SMEM);

    static cudaStream_t sZ = nullptr, sBA = nullptr, sWo = nullptr;
    static cudaEvent_t evRoot, evX, evZ, evBA, evWo;
    if (!sZ) {
        cudaStreamCreateWithFlags(&sZ,  cudaStreamNonBlocking);
        cudaStreamCreateWithFlags(&sBA, cudaStreamNonBlocking);
        cudaStreamCreateWithFlags(&sWo, cudaStreamNonBlocking);
        cudaEventCreateWithFlags(&evRoot, cudaEventDisableTiming);
        cudaEventCreateWithFlags(&evX,    cudaEventDisableTiming);
        cudaEventCreateWithFlags(&evZ,    cudaEventDisableTiming);
        cudaEventCreateWithFlags(&evBA,   cudaEventDisableTiming);
        cudaEventCreateWithFlags(&evWo,   cudaEventDisableTiming);
    }

    // ---- fork ----
    cudaEventRecord(evRoot, 0);
    cudaStreamWaitEvent(sZ,  evRoot, 0);
    cudaStreamWaitEvent(sBA, evRoot, 0);
    cudaStreamWaitEvent(sWo, evRoot, 0);

    // main: x cvt -> qkv GEMM -> conv -> qk -> recur -> rmsnorm -> out GEMM
    cvt_half<<<(BT_*C_/4 + 255)/256, 256>>>(x, p_xh, BT_*C_/4);
    cudaEventRecord(evX, 0);
    cvt_half<<<(CONV_DIM_*C_/4 + 255)/256, 256>>>(W_qkv, p_Wqh, CONV_DIM_*C_/4);
    hgemm_nt<<<dim3(CONV_DIM_/128, BT_/128), 256, HG_SMEM>>>(p_xh, p_Wqh, p_qkv, BT_, CONV_DIM_, C_);
    conv_kernel<<<BT_, 256>>>(conv_w, conv_state, input_pos);
    qk_kernel<<<B_ * NHK_ * NCH, 256, QK_SMEM>>>();

    // z branch
    cvt_half<<<(VAL_DIM_*C_/4 + 255)/256, 256, 0, sZ>>>(W_z, p_Wzh, VAL_DIM_*C_/4);
    cudaStreamWaitEvent(sZ, evX, 0);
    hgemm_nt<<<dim3(VAL_DIM_/128, BT_/128), 256, HG_SMEM, sZ>>>(p_xh, p_Wzh, p_z, BT_, VAL_DIM_, C_);
    cudaEventRecord(evZ, sZ);

    // b/a branch
    zero_kernel<<<(BT_*64 + 255)/256, 256, 0, sBA>>>(p_ba, BT_*64);
    sgemm_ba<<<dim3(1, BT_/128, 8), 256, 0, sBA>>>(x, W_b, W_a, p_ba, BT_, C_);
    betag_kernel<<<(BT_ * NV_ + 255) / 256, 256, 0, sBA>>>(dt_bias, A_log);
    cudaEventRecord(evBA, sBA);

    // Wo branch
    cvt_half<<<(C_*VAL_DIM_/4 + 255)/256, 256, 0, sWo>>>(W_out, p_Woh, C_*VAL_DIM_/4);
    cudaEventRecord(evWo, sWo);

    // join
    cudaStreamWaitEvent(0, evBA, 0);
    recur_kernel<<<B_ * NV_ * SPLITV, 512, RECUR_SMEM>>>(rstate, input_pos);

    cudaStreamWaitEvent(0, evZ, 0);
    rmsnorm_kernel<<<BT_ * NV_, 128>>>(norm_w);

    cudaStreamWaitEvent(0, evWo, 0);
    hgemm_nt<<<dim3(C_/128, BT_/128), 256, HG_SMEM>>>(p_oh, p_Woh, out, BT_, C_, VAL_DIM_);
}

// round 6
// speedup vs baseline: 4.9173x; 1.0118x over previous
#include <cuda_runtime.h>
#include <cuda_fp16.h>
#include <math.h>
#include <stdint.h>

#define B_ 2
#define T_ 2048
#define C_ 2048
#define NV_ 32
#define NHK_ 16
#define DK_ 128
#define DV_ 128
#define KEY_DIM_ 2048
#define VAL_DIM_ 4096
#define CONV_DIM_ 8192
#define BT_ (B_*T_)
#define LCH 64
#define NCH (T_/LCH)
#define SPLITV 2
#define DVS (DV_/SPLITV)
#define CTT 8

// ---------------- scratch (static device globals; no allocation) ----------------
__device__ float g_qkv [BT_*CONV_DIM_];
__device__ float g_z   [BT_*VAL_DIM_];
__device__ float g_q   [BT_*KEY_DIM_];
__device__ float g_k   [BT_*KEY_DIM_];
__device__ float g_v   [BT_*VAL_DIM_];
__device__ float g_ba  [BT_*64];
__device__ float g_beta[BT_*NV_];
__device__ float g_gg  [BT_*NV_];
__device__ float g_o   [BT_*VAL_DIM_];
__device__ float g_qk  [(size_t)B_*NHK_*NCH*LCH*LCH];

__device__ __half g_xh [BT_*C_];
__device__ __half g_Wqh[CONV_DIM_*C_];
__device__ __half g_Wzh[VAL_DIM_*C_];
__device__ __half g_Woh[C_*VAL_DIM_];
__device__ __half g_oh [BT_*VAL_DIM_];

// ---------------- helpers ----------------
__device__ __forceinline__ uint32_t smem_u32(const void* p) {
    uint32_t a;
    asm("{ .reg .u64 t; cvta.to.shared.u64 t, %1; cvt.u32.u64 %0, t; }" : "=r"(a) : "l"(p));
    return a;
}
__device__ __forceinline__ void ldsm_x4(uint32_t& r0, uint32_t& r1, uint32_t& r2, uint32_t& r3, uint32_t addr) {
    asm volatile("ldmatrix.sync.aligned.m8n8.x4.shared.b16 {%0,%1,%2,%3}, [%4];"
                 : "=r"(r0), "=r"(r1), "=r"(r2), "=r"(r3) : "r"(addr));
}
__device__ __forceinline__ void mma16816(float* c, uint32_t a0, uint32_t a1, uint32_t a2, uint32_t a3,
                                         uint32_t b0, uint32_t b1) {
    asm volatile("mma.sync.aligned.m16n8k16.row.col.f32.f16.f16.f32 "
                 "{%0,%1,%2,%3}, {%4,%5,%6,%7}, {%8,%9}, {%0,%1,%2,%3};"
                 : "+f"(c[0]), "+f"(c[1]), "+f"(c[2]), "+f"(c[3])
                 : "r"(a0), "r"(a1), "r"(a2), "r"(a3), "r"(b0), "r"(b1));
}
#define CP_ASYNC16(dst, src) asm volatile("cp.async.cg.shared.global [%0], [%1], 16;" :: "r"(dst), "l"(src))
#define CP_COMMIT()          asm volatile("cp.async.commit_group;" ::: "memory")
#define CP_WAIT2()           asm volatile("cp.async.wait_group 2;" ::: "memory")

// ---------------- fp16 HGEMM: C[M,N] = A[M,K] * B[N,K]^T, 4-stage cp.async ----------------
__global__ __launch_bounds__(256, 2)
void hgemm_nt(const __half* __restrict__ A, const __half* __restrict__ Bm,
              float* __restrict__ C, int M, int N, int K)
{
    extern __shared__ __half hsm[];
    const int STG = 128 * 40;
    __half* AsP = hsm;
    __half* BsP = hsm + 4 * STG;

    int tid = threadIdx.x;
    int lane = tid & 31, wid = tid >> 5;
    int wm = wid & 1, wn = wid >> 1;
    int m0w = wm * 64, n0w = wn * 32;
    int row0 = blockIdx.y * 128, col0 = blockIdx.x * 128;

    uint32_t aBase = smem_u32(AsP);
    uint32_t bBase = smem_u32(BsP);

    float acc[4][4][4];
#pragma unroll
    for (int i = 0; i < 4; i++)
#pragma unroll
        for (int j = 0; j < 4; j++)
#pragma unroll
            for (int e = 0; e < 4; e++) acc[i][j][e] = 0.f;

    const int NT = K >> 5;
    int lr = tid >> 2, lc = (tid & 3) << 3;
    int lr1 = lr + 64;

    auto issue = [&](int kt, int s) {
        int k0 = kt << 5;
        CP_ASYNC16(aBase + ((s * STG + lr  * 40 + lc) << 1), A  + (size_t)(row0 + lr ) * K + k0 + lc);
        CP_ASYNC16(aBase + ((s * STG + lr1 * 40 + lc) << 1), A  + (size_t)(row0 + lr1) * K + k0 + lc);
        CP_ASYNC16(bBase + ((s * STG + lr  * 40 + lc) << 1), Bm + (size_t)(col0 + lr ) * K + k0 + lc);
        CP_ASYNC16(bBase + ((s * STG + lr1 * 40 + lc) << 1), Bm + (size_t)(col0 + lr1) * K + k0 + lc);
        CP_COMMIT();
    };

    issue(0, 0);
    issue(1, 1);
    issue(2, 2);

    for (int kt = 0; kt < NT; kt++) {
        CP_WAIT2();
        __syncthreads();
        if (kt + 3 < NT) issue(kt + 3, (kt + 3) & 3);
        int s = kt & 3;
#pragma unroll
        for (int kk = 0; kk < 32; kk += 16) {
            uint32_t a[4][4], b[4][2];
#pragma unroll
            for (int i = 0; i < 4; i++) {
                int r = m0w + i * 16 + (lane & 15);
                int c = kk + ((lane >> 4) << 3);
                ldsm_x4(a[i][0], a[i][1], a[i][2], a[i][3],
                        aBase + ((s * STG + r * 40 + c) << 1));
            }
#pragma unroll
            for (int j = 0; j < 2; j++) {
                int q = lane >> 3, rr = lane & 7;
                int r = n0w + j * 16 + ((q >> 1) << 3) + rr;
                int c = kk + ((q & 1) << 3);
                uint32_t t0, t1, t2, t3;
                ldsm_x4(t0, t1, t2, t3, bBase + ((s * STG + r * 40 + c) << 1));
                b[2*j][0] = t0; b[2*j][1] = t1; b[2*j+1][0] = t2; b[2*j+1][1] = t3;
            }
#pragma unroll
            for (int i = 0; i < 4; i++)
#pragma unroll
                for (int j = 0; j < 4; j++)
                    mma16816(acc[i][j], a[i][0], a[i][1], a[i][2], a[i][3], b[j][0], b[j][1]);
        }
        __syncthreads();
    }

#pragma unroll
    for (int i = 0; i < 4; i++) {
        int r = row0 + m0w + i * 16 + (lane >> 2);
#pragma unroll
        for (int j = 0; j < 4; j++) {
            int c = col0 + n0w + j * 8 + ((lane & 3) << 1);
            *(float2*)&C[(size_t)r * N + c]       = make_float2(acc[i][j][0], acc[i][j][1]);
            *(float2*)&C[(size_t)(r + 8) * N + c] = make_float2(acc[i][j][2], acc[i][j][3]);
        }
    }
}

// ---------------- fp32 -> fp16 convert ----------------
__global__ void cvt_half(const float* __restrict__ in, __half* __restrict__ out, int n4)
{
    int i = blockIdx.x * blockDim.x + threadIdx.x;
    if (i >= n4) return;
    float4 v = ((const float4*)in)[i];
    union { __half h[4]; uint2 u; } p;
    p.h[0] = __float2half_rn(v.x); p.h[1] = __float2half_rn(v.y);
    p.h[2] = __float2half_rn(v.z); p.h[3] = __float2half_rn(v.w);
    ((uint2*)out)[i] = p.u;
}

__global__ void zero_kernel(float* p, int n)
{
    int i = blockIdx.x * blockDim.x + threadIdx.x;
    if (i < n) p[i] = 0.f;
}

// ---------------- fp32 split-K GEMM for b|a ----------------
__global__ void sgemm_ba(const float* __restrict__ A, const float* __restrict__ Wb,
                         const float* __restrict__ Wa, float* __restrict__ C, int M, int K)
{
    __shared__ float As[16][128];
    __shared__ float Bs[16][64];
    int tid = threadIdx.x;
    int tx = tid & 15, ty = tid >> 4;
    int row0 = blockIdx.y * 128;
    int kBeg = blockIdx.z * (K / 8), kEnd = kBeg + K / 8;

    float acc[8][4];
#pragma unroll
    for (int m = 0; m < 8; m++)
#pragma unroll
        for (int n = 0; n < 4; n++) acc[m][n] = 0.f;

    for (int kt = kBeg; kt < kEnd; kt += 16) {
#pragma unroll
        for (int i = 0; i < 2; i++) {
            int f = tid + i * 256;
            int r = f >> 2, c4 = (f & 3) << 2;
            float4 av = *(const float4*)(A + (size_t)(row0 + r) * K + kt + c4);
            As[c4][r] = av.x; As[c4+1][r] = av.y; As[c4+2][r] = av.z; As[c4+3][r] = av.w;
        }
        {
            int r = tid >> 2, c4 = (tid & 3) << 2;
            if (r < 64) {
                const float* src = (r < 32) ? (Wb + (size_t)r * K) : (Wa + (size_t)(r - 32) * K);
                float4 bv = *(const float4*)(src + kt + c4);
                Bs[c4][r] = bv.x; Bs[c4+1][r] = bv.y; Bs[c4+2][r] = bv.z; Bs[c4+3][r] = bv.w;
            }
        }
        __syncthreads();
#pragma unroll
        for (int k = 0; k < 16; k++) {
            float ra[8], rb[4];
            *(float4*)&ra[0] = *(float4*)&As[k][ty * 8];
            *(float4*)&ra[4] = *(float4*)&As[k][ty * 8 + 4];
            *(float4*)&rb[0] = *(float4*)&Bs[k][tx * 4];
#pragma unroll
            for (int m = 0; m < 8; m++)
#pragma unroll
                for (int n = 0; n < 4; n++) acc[m][n] += ra[m] * rb[n];
        }
        __syncthreads();
    }
#pragma unroll
    for (int m = 0; m < 8; m++) {
        int gr = row0 + ty * 8 + m;
#pragma unroll
        for (int n = 0; n < 4; n++)
            atomicAdd(&C[(size_t)gr * 64 + tx * 4 + n], acc[m][n]);
    }
}

// ---------------- beta / g finalize ----------------
__global__ void betag_kernel(const float* __restrict__ dt_bias, const float* __restrict__ A_log)
{
    int i = blockIdx.x * blockDim.x + threadIdx.x;
    if (i >= BT_ * NV_) return;
    int bt = i >> 5, h = i & 31;
    float braw = g_ba[bt * 64 + h];
    float araw = g_ba[bt * 64 + 32 + h];
    g_beta[i] = 1.f / (1.f + expf(-braw));
    float a = araw + dt_bias[h];
    float sp = (a > 20.f) ? a : log1pf(expf(a));
    g_gg[i] = -expf(A_log[h]) * sp;
}

// ---------------- causal depthwise conv(K=4) + silu, tiled over 8 timesteps ----------------
__global__ __launch_bounds__(256)
void conv_kernel(const float* __restrict__ conv_w,
                 const float* __restrict__ conv_state,
                 const int* __restrict__ input_pos)
{
    int blk = blockIdx.x;
    int b = blk / (T_ / CTT);
    int t0 = (blk % (T_ / CTT)) * CTT;
    int tid = threadIdx.x;
    float keep = (input_pos[0] == 0) ? 0.f : 1.f;

    for (int d = tid; d < CONV_DIM_; d += 256) {
        float4 w = *(const float4*)(conv_w + (size_t)d * 4);
        float xv[CTT + 3];
#pragma unroll
        for (int j = 0; j < CTT + 3; j++) {
            int tt = t0 - 3 + j;
            if (tt >= 0) xv[j] = g_qkv[(size_t)(b * T_ + tt) * CONV_DIM_ + d];
            else         xv[j] = keep * conv_state[((size_t)b * CONV_DIM_ + d) * 4 + (tt + 4)];
        }
#pragma unroll
        for (int to = 0; to < CTT; to++) {
            float acc = w.x * xv[to] + w.y * xv[to+1] + w.z * xv[to+2] + w.w * xv[to+3];
            float s = acc / (1.f + expf(-acc));
            size_t bt = (size_t)(b * T_ + t0 + to);
            if (d < 2048)      g_q[bt * KEY_DIM_ + d] = s;
            else if (d < 4096) g_k[bt * KEY_DIM_ + (d - 2048)] = s;
            else               g_v[bt * VAL_DIM_ + (d - 4096)] = s;
        }
    }
}

// ---------------- q/k L2 normalization: one warp per (bt, head-slot) ----------------
__global__ __launch_bounds__(256)
void qknorm_kernel()
{
    int gw = blockIdx.x * 8 + (threadIdx.x >> 5);
    int lane = threadIdx.x & 31;
    int bt = gw >> 5, s = gw & 31;
    float* base = (s < 16) ? (g_q + (size_t)bt * KEY_DIM_ + s * 128)
                           : (g_k + (size_t)bt * KEY_DIM_ + (s - 16) * 128);
    float4 v = *(float4*)(base + lane * 4);
    float ss = v.x*v.x + v.y*v.y + v.z*v.z + v.w*v.w;
#pragma unroll
    for (int off = 16; off; off >>= 1) ss += __shfl_xor_sync(0xffffffffu, ss, off);
    float inv = 1.f / fmaxf(sqrtf(ss), 1e-12f);
    v.x *= inv; v.y *= inv; v.z *= inv; v.w *= inv;
    *(float4*)(base + lane * 4) = v;
}

// ---------------- QK precompute ----------------
__global__ __launch_bounds__(256)
void qk_kernel()
{
    extern __shared__ float qsm[];
    float* sq = qsm;
    float* sk = qsm + 64 * 132;

    int bidx = blockIdx.x;
    int ch = bidx % NCH;
    int hk = (bidx / NCH) % NHK_;
    int b  = bidx / (NCH * NHK_);
    int t0 = ch * LCH;
    int tid = threadIdx.x;
    int tx = tid & 15, ty = tid >> 4;

    for (int f = tid; f < 64 * 32; f += 256) {
        int r = f >> 5, c = (f & 31) * 4;
        *(float4*)&sq[r * 132 + c] = *(const float4*)(g_q + (size_t)(b * T_ + t0 + r) * KEY_DIM_ + hk * DK_ + c);
        *(float4*)&sk[r * 132 + c] = *(const float4*)(g_k + (size_t)(b * T_ + t0 + r) * KEY_DIM_ + hk * DK_ + c);
    }
    __syncthreads();

    float accA[4][4];
#pragma unroll
    for (int a = 0; a < 4; a++)
#pragma unroll
        for (int c = 0; c < 4; c++) accA[a][c] = 0.f;

    if (tx * 4 <= ty * 4 + 3) {
        for (int k4 = 0; k4 < DK_; k4 += 4) {
            float4 kb[4];
#pragma unroll
            for (int c = 0; c < 4; c++) kb[c] = *(float4*)&sk[(tx * 4 + c) * 132 + k4];
#pragma unroll
            for (int a = 0; a < 4; a++) {
                float4 qa = *(float4*)&sq[(ty * 4 + a) * 132 + k4];
#pragma unroll
                for (int c = 0; c < 4; c++)
                    accA[a][c] += qa.x * kb[c].x + qa.y * kb[c].y + qa.z * kb[c].z + qa.w * kb[c].w;
            }
        }
    }
    float* dst = g_qk + (size_t)bidx * (LCH * LCH);
#pragma unroll
    for (int a = 0; a < 4; a++) {
        float4 w = make_float4(accA[a][0], accA[a][1], accA[a][2], accA[a][3]);
        *(float4*)&dst[(ty * 4 + a) * 64 + tx * 4] = w;
    }
}

// ---------------- chunked gated linear-attention recurrence (512 threads) ----------------
__device__ __forceinline__ void fma4(float4& a, float s, const float4 b)
{ a.x += s * b.x; a.y += s * b.y; a.z += s * b.z; a.w += s * b.w; }

__global__ __launch_bounds__(512)
void recur_kernel(const float* __restrict__ rstate, const int* __restrict__ input_pos)
{
    extern __shared__ float sm[];
    float* sq = sm;
    float* sk = sq + 64 * 132;
    float* sv = sk + 64 * 132;
    float* sA = sv + 64 * 68;
    float* sS = sA + 64 * 68;
    float* sG = sS + 128 * 68;
    float* sB = sG + 64;
    float* sW = sB + 64;

    int bidx = blockIdx.x;
    int vs = bidx & 1;
    int h  = (bidx >> 1) & (NV_ - 1);
    int b  = bidx >> 6;
    int hk = h >> 1;
    int tid = threadIdx.x;
    int tx = tid & 15, ty = tid >> 4;
    float keep = (input_pos[0] == 0) ? 0.f : 1.f;

#pragma unroll
    for (int j = 0; j < 4; j++) {
        int kk = ty * 4 + j;
        float4 v4 = *(const float4*)(rstate + (((size_t)(b * NV_ + h)) * DK_ + kk) * DV_ + vs * DVS + tx * 4);
        v4.x *= keep; v4.y *= keep; v4.z *= keep; v4.w *= keep;
        *(float4*)&sS[kk * 68 + tx * 4] = v4;
    }

    const float* qkBase = g_qk + ((size_t)(b * NHK_ + hk) * NCH) * (LCH * LCH);

    for (int ch = 0; ch < NCH; ch++) {
        int t0 = ch * LCH;
        __syncthreads();
        for (int f = tid; f < 64 * 32; f += 512) {
            int r = f >> 5, c = (f & 31) * 4;
            *(float4*)&sq[r * 132 + c] = *(const float4*)(g_q + (size_t)(b * T_ + t0 + r) * KEY_DIM_ + hk * DK_ + c);
            *(float4*)&sk[r * 132 + c] = *(const float4*)(g_k + (size_t)(b * T_ + t0 + r) * KEY_DIM_ + hk * DK_ + c);
        }
        for (int f = tid; f < 64 * 16; f += 512) {
            int r = f >> 4, c = (f & 15) * 4;
            *(float4*)&sv[r * 68 + c] = *(const float4*)(g_v + (size_t)(b * T_ + t0 + r) * VAL_DIM_ + h * DV_ + vs * DVS + c);
        }
        if (tid < 64) {
            sB[tid] = g_beta[(b * T_ + t0 + tid) * NV_ + h];
            sG[tid] = g_gg  [(b * T_ + t0 + tid) * NV_ + h];
        }
        __syncthreads();
        if (tid == 0) {
            float run = 0.f;
            for (int i = 0; i < LCH; i++) { run += sG[i]; sG[i] = run; }
        }
        __syncthreads();
        if (tid < 64) {
            float df = sG[63] - sG[tid];
            sW[tid] = (df > -30.f) ? expf(df) * sB[tid] : 0.f;
        }

        // sA[t][i] = QK[t][i] * exp(Gt - Gi) * beta_i, masked i<=t
        {
            const float* qkT = qkBase + (size_t)ch * (LCH * LCH);
            int f0 = tid * 8;
            int t = f0 >> 6, i0 = f0 & 63;
            float gt = sG[t];
            float4 qa = *(const float4*)(qkT + t * 64 + i0);
            float4 qb = *(const float4*)(qkT + t * 64 + i0 + 4);
            float r[8] = {qa.x, qa.y, qa.z, qa.w, qb.x, qb.y, qb.z, qb.w};
#pragma unroll
            for (int j = 0; j < 8; j++) {
                int i = i0 + j;
                float d = gt - sG[i];
                r[j] = (i <= t && d > -30.f) ? r[j] * expf(d) * sB[i] : 0.f;
            }
            *(float4*)&sA[t * 68 + i0]     = make_float4(r[0], r[1], r[2], r[3]);
            *(float4*)&sA[t * 68 + i0 + 4] = make_float4(r[4], r[5], r[6], r[7]);
        }
        __syncthreads();

        int r0 = ty * 2, r1 = r0 + 1;
        float4 acc[2], acci[2];
#pragma unroll
        for (int a = 0; a < 2; a++) { acc[a] = make_float4(0,0,0,0); acci[a] = make_float4(0,0,0,0); }

        // intra: A @ V with causal break + decay skip
        float gr0 = sG[r0];
        for (int i4 = 0; i4 < LCH; i4 += 4) {
            if (i4 > r1) break;
            if (i4 + 3 < r0 && gr0 - sG[i4 + 3] < -30.f) continue;
            float4 vv[4];
#pragma unroll
            for (int ii = 0; ii < 4; ii++) vv[ii] = *(float4*)&sv[(i4 + ii) * 68 + tx * 4];
#pragma unroll
            for (int a = 0; a < 2; a++) {
                float4 av = *(float4*)&sA[(r0 + a) * 68 + i4];
                fma4(acc[a], av.x, vv[0]); fma4(acc[a], av.y, vv[1]);
                fma4(acc[a], av.z, vv[2]); fma4(acc[a], av.w, vv[3]);
            }
        }
        // inter: q @ S, skipped entirely when e^{G_t} negligible
        if (gr0 > -30.f) {
            for (int k4 = 0; k4 < DK_; k4 += 4) {
                float4 ssr[4];
#pragma unroll
                for (int kk = 0; kk < 4; kk++) ssr[kk] = *(float4*)&sS[(k4 + kk) * 68 + tx * 4];
#pragma unroll
                for (int a = 0; a < 2; a++) {
                    float4 qa = *(float4*)&sq[(r0 + a) * 132 + k4];
                    fma4(acci[a], qa.x, ssr[0]); fma4(acci[a], qa.y, ssr[1]);
                    fma4(acci[a], qa.z, ssr[2]); fma4(acci[a], qa.w, ssr[3]);
                }
            }
        }
#pragma unroll
        for (int a = 0; a < 2; a++) {
            int t = r0 + a;
            float et = expf(sG[t]);
            float4 w4 = make_float4(acc[a].x + et * acci[a].x, acc[a].y + et * acci[a].y,
                                    acc[a].z + et * acci[a].z, acc[a].w + et * acci[a].w);
            *(float4*)(g_o + (size_t)(b * T_ + t0 + t) * VAL_DIM_ + h * DV_ + vs * DVS + tx * 4) = w4;
        }
        __syncthreads();

        // S = exp(G_last)*S + sum_i w_i * k_i (outer) v_i, skipping w_i == 0
        float elast = expf(sG[63]);
        float4 Sreg[4];
#pragma unroll
        for (int j = 0; j < 4; j++) {
            Sreg[j] = *(float4*)&sS[(ty * 4 + j) * 68 + tx * 4];
            Sreg[j].x *= elast; Sreg[j].y *= elast; Sreg[j].z *= elast; Sreg[j].w *= elast;
        }
        for (int i = 0; i < LCH; i++) {
            float w = sW[i];
            if (w == 0.f) continue;
            float4 vv = *(float4*)&sv[i * 68 + tx * 4];
            float4 k0 = *(float4*)&sk[i * 132 + ty * 4];
            fma4(Sreg[0], w * k0.x, vv); fma4(Sreg[1], w * k0.y, vv);
            fma4(Sreg[2], w * k0.z, vv); fma4(Sreg[3], w * k0.w, vv);
        }
#pragma unroll
        for (int j = 0; j < 4; j++)
            *(float4*)&sS[(ty * 4 + j) * 68 + tx * 4] = Sreg[j];
    }
}

// ---------------- gated RMSNorm -> fp16 ----------------
__global__ void rmsnorm_kernel(const float* __restrict__ norm_w)
{
    int bh = blockIdx.x;
    int bt = bh >> 5, h = bh & 31;
    int tid = threadIdx.x;
    long idx = (long)bt * VAL_DIM_ + h * DV_ + tid;
    float o = g_o[idx];
    float z = g_z[idx];
    float val = o * (z / (1.f + expf(-z)));
    float s = val * val;
#pragma unroll
    for (int off = 16; off; off >>= 1) s += __shfl_xor_sync(0xffffffffu, s, off);
    __shared__ float red[4];
    int warp = tid >> 5, lane = tid & 31;
    if (lane == 0) red[warp] = s;
    __syncthreads();
    float tot = red[0] + red[1] + red[2] + red[3];
    float scale = rsqrtf(tot * (1.f / 128.f) + 1e-6f) * norm_w[tid];
    g_oh[idx] = __float2half_rn(val * scale);
}

// ---------------- launch (fork-join multi-stream, graph-capturable) ----------------
extern "C" void kernel_launch(void* const* d_in, const int* in_sizes, int n_in,
                              void* d_out, int out_size)
{
    const float* x          = (const float*)d_in[0];
    const int*   input_pos  = (const int*)  d_in[1];
    const float* W_qkv      = (const float*)d_in[2];
    const float* W_z        = (const float*)d_in[3];
    const float* W_b        = (const float*)d_in[4];
    const float* W_a        = (const float*)d_in[5];
    const float* conv_w     = (const float*)d_in[6];
    const float* dt_bias    = (const float*)d_in[7];
    const float* A_log      = (const float*)d_in[8];
    const float* norm_w     = (const float*)d_in[9];
    const float* W_out      = (const float*)d_in[10];
    const float* conv_state = (const float*)d_in[11];
    const float* rstate     = (const float*)d_in[12];
    float* out = (float*)d_out;

    float *p_qkv, *p_z, *p_ba;
    __half *p_xh, *p_Wqh, *p_Wzh, *p_Woh, *p_oh;
    cudaGetSymbolAddress((void**)&p_qkv, g_qkv);
    cudaGetSymbolAddress((void**)&p_z,   g_z);
    cudaGetSymbolAddress((void**)&p_ba,  g_ba);
    cudaGetSymbolAddress((void**)&p_xh,  g_xh);
    cudaGetSymbolAddress((void**)&p_Wqh, g_Wqh);
    cudaGetSymbolAddress((void**)&p_Wzh, g_Wzh);
    cudaGetSymbolAddress((void**)&p_Woh, g_Woh);
    cudaGetSymbolAddress((void**)&p_oh,  g_oh);

    const int RECUR_SMEM = (64*132*2 + 64*68*2 + 128*68 + 64*3) * 4;   // 137984 B
    const int QK_SMEM    = (64*132*2) * 4;                              // 67584 B
    const int HG_SMEM    = 8 * 128 * 40 * 2;                            // 81920 B
    cudaFuncSetAttribute(recur_kernel, cudaFuncAttributeMaxDynamicSharedMemorySize, RECUR_SMEM);
    cudaFuncSetAttribute(qk_kernel,    cudaFuncAttributeMaxDynamicSharedMemorySize, QK_SMEM);
    cudaFuncSetAttribute(hgemm_nt,     cudaFuncAttributeMaxDynamicSharedMemorySize, HG_SMEM);

    static cudaStream_t sZ = nullptr, sBA = nullptr, sWo = nullptr;
    static cudaEvent_t evRoot, evX, evZ, evBA, evWo;
    if (!sZ) {
        cudaStreamCreateWithFlags(&sZ,  cudaStreamNonBlocking);
        cudaStreamCreateWithFlags(&sBA, cudaStreamNonBlocking);
        cudaStreamCreateWithFlags(&sWo, cudaStreamNonBlocking);
        cudaEventCreateWithFlags(&evRoot, cudaEventDisableTiming);
        cudaEventCreateWithFlags(&evX,    cudaEventDisableTiming);
        cudaEventCreateWithFlags(&evZ,    cudaEventDisableTiming);
        cudaEventCreateWithFlags(&evBA,   cudaEventDisableTiming);
        cudaEventCreateWithFlags(&evWo,   cudaEventDisableTiming);
    }

    // ---- fork ----
    cudaEventRecord(evRoot, 0);
    cudaStreamWaitEvent(sZ,  evRoot, 0);
    cudaStreamWaitEvent(sBA, evRoot, 0);
    cudaStreamWaitEvent(sWo, evRoot, 0);

    // main: x cvt -> qkv GEMM -> conv -> qknorm -> qk -> recur -> rmsnorm -> out GEMM
    cvt_half<<<(BT_*C_/4 + 255)/256, 256>>>(x, p_xh, BT_*C_/4);
    cudaEventRecord(evX, 0);
    cvt_half<<<(CONV_DIM_*C_/4 + 255)/256, 256>>>(W_qkv, p_Wqh, CONV_DIM_*C_/4);
    hgemm_nt<<<dim3(CONV_DIM_/128, BT_/128), 256, HG_SMEM>>>(p_xh, p_Wqh, p_qkv, BT_, CONV_DIM_, C_);
    conv_kernel<<<BT_/CTT, 256>>>(conv_w, conv_state, input_pos);
    qknorm_kernel<<<BT_*32/8, 256>>>();
    qk_kernel<<<B_ * NHK_ * NCH, 256, QK_SMEM>>>();

    // z branch
    cvt_half<<<(VAL_DIM_*C_/4 + 255)/256, 256, 0, sZ>>>(W_z, p_Wzh, VAL_DIM_*C_/4);
    cudaStreamWaitEvent(sZ, evX, 0);
    hgemm_nt<<<dim3(VAL_DIM_/128, BT_/128), 256, HG_SMEM, sZ>>>(p_xh, p_Wzh, p_z, BT_, VAL_DIM_, C_);
    cudaEventRecord(evZ, sZ);

    // b/a branch
    zero_kernel<<<(BT_*64 + 255)/256, 256, 0, sBA>>>(p_ba, BT_*64);
    sgemm_ba<<<dim3(1, BT_/128, 8), 256, 0, sBA>>>(x, W_b, W_a, p_ba, BT_, C_);
    betag_kernel<<<(BT_ * NV_ + 255) / 256, 256, 0, sBA>>>(dt_bias, A_log);
    cudaEventRecord(evBA, sBA);

    // Wo branch
    cvt_half<<<(C_*VAL_DIM_/4 + 255)/256, 256, 0, sWo>>>(W_out, p_Woh, C_*VAL_DIM_/4);
    cudaEventRecord(evWo, sWo);

    // join
    cudaStreamWaitEvent(0, evBA, 0);
    recur_kernel<<<B_ * NV_ * SPLITV, 512, RECUR_SMEM>>>(rstate, input_pos);

    cudaStreamWaitEvent(0, evZ, 0);
    rmsnorm_kernel<<<BT_ * NV_, 128>>>(norm_w);

    cudaStreamWaitEvent(0, evWo, 0);
    hgemm_nt<<<dim3(C_/128, BT_/128), 256, HG_SMEM>>>(p_oh, p_Woh, out, BT_, C_, VAL_DIM_);
}

// round 7
// speedup vs baseline: 5.1391x; 1.0451x over previous
#include <cuda_runtime.h>
#include <cuda_fp16.h>
#include <math.h>
#include <stdint.h>

#define B_ 2
#define T_ 2048
#define C_ 2048
#define NV_ 32
#define NHK_ 16
#define DK_ 128
#define DV_ 128
#define KEY_DIM_ 2048
#define VAL_DIM_ 4096
#define CONV_DIM_ 8192
#define BT_ (B_*T_)
#define LCH 64
#define NCH (T_/LCH)
#define SPLITV 2
#define DVS (DV_/SPLITV)
#define CTT 8

typedef unsigned long long ull;

// ---------------- scratch (static device globals; no allocation) ----------------
__device__ float g_qkv [BT_*CONV_DIM_];
__device__ float g_z   [BT_*VAL_DIM_];
__device__ float g_q   [BT_*KEY_DIM_];
__device__ float g_k   [BT_*KEY_DIM_];
__device__ float g_v   [BT_*VAL_DIM_];
__device__ float g_ba  [BT_*64];
__device__ float g_beta[BT_*NV_];
__device__ float g_gg  [BT_*NV_];
__device__ float g_o   [BT_*VAL_DIM_];
__device__ float g_qk  [(size_t)B_*NHK_*NCH*LCH*LCH];

__device__ __half g_xh [BT_*C_];
__device__ __half g_Wqh[CONV_DIM_*C_];
__device__ __half g_Wzh[VAL_DIM_*C_];
__device__ __half g_Woh[C_*VAL_DIM_];
__device__ __half g_oh [BT_*VAL_DIM_];

// ---------------- helpers ----------------
__device__ __forceinline__ uint32_t smem_u32(const void* p) {
    uint32_t a;
    asm("{ .reg .u64 t; cvta.to.shared.u64 t, %1; cvt.u32.u64 %0, t; }" : "=r"(a) : "l"(p));
    return a;
}
__device__ __forceinline__ void ldsm_x4(uint32_t& r0, uint32_t& r1, uint32_t& r2, uint32_t& r3, uint32_t addr) {
    asm volatile("ldmatrix.sync.aligned.m8n8.x4.shared.b16 {%0,%1,%2,%3}, [%4];"
                 : "=r"(r0), "=r"(r1), "=r"(r2), "=r"(r3) : "r"(addr));
}
__device__ __forceinline__ void mma16816(float* c, uint32_t a0, uint32_t a1, uint32_t a2, uint32_t a3,
                                         uint32_t b0, uint32_t b1) {
    asm volatile("mma.sync.aligned.m16n8k16.row.col.f32.f16.f16.f32 "
                 "{%0,%1,%2,%3}, {%4,%5,%6,%7}, {%8,%9}, {%0,%1,%2,%3};"
                 : "+f"(c[0]), "+f"(c[1]), "+f"(c[2]), "+f"(c[3])
                 : "r"(a0), "r"(a1), "r"(a2), "r"(a3), "r"(b0), "r"(b1));
}
#define CP_ASYNC16(dst, src) asm volatile("cp.async.cg.shared.global [%0], [%1], 16;" :: "r"(dst), "l"(src))
#define CP_COMMIT()          asm volatile("cp.async.commit_group;" ::: "memory")
#define CP_WAIT2()           asm volatile("cp.async.wait_group 2;" ::: "memory")

// ---- packed fp32x2 (sm_100-family) ----
__device__ __forceinline__ ull bcast2(float s) {
    ull r; asm("mov.b64 %0, {%1, %1};" : "=l"(r) : "f"(s)); return r;
}
__device__ __forceinline__ void fma2(ull& a, ull s, ull b) {
    asm("fma.rn.f32x2 %0, %1, %2, %0;" : "+l"(a) : "l"(s), "l"(b));
}
__device__ __forceinline__ void mul2(ull& a, ull b) {
    asm("mul.rn.f32x2 %0, %0, %1;" : "+l"(a) : "l"(b));
}
__device__ __forceinline__ float2 unpack2(ull a) {
    float2 f; asm("mov.b64 {%0, %1}, %2;" : "=f"(f.x), "=f"(f.y) : "l"(a)); return f;
}

// ---------------- fp16 HGEMM: C[M,N] = A[M,K] * B[N,K]^T, 4-stage cp.async ----------------
__global__ __launch_bounds__(256, 2)
void hgemm_nt(const __half* __restrict__ A, const __half* __restrict__ Bm,
              float* __restrict__ C, int M, int N, int K)
{
    extern __shared__ __half hsm[];
    const int STG = 128 * 40;
    __half* AsP = hsm;
    __half* BsP = hsm + 4 * STG;

    int tid = threadIdx.x;
    int lane = tid & 31, wid = tid >> 5;
    int wm = wid & 1, wn = wid >> 1;
    int m0w = wm * 64, n0w = wn * 32;
    int row0 = blockIdx.y * 128, col0 = blockIdx.x * 128;

    uint32_t aBase = smem_u32(AsP);
    uint32_t bBase = smem_u32(BsP);

    float acc[4][4][4];
#pragma unroll
    for (int i = 0; i < 4; i++)
#pragma unroll
        for (int j = 0; j < 4; j++)
#pragma unroll
            for (int e = 0; e < 4; e++) acc[i][j][e] = 0.f;

    const int NT = K >> 5;
    int lr = tid >> 2, lc = (tid & 3) << 3;
    int lr1 = lr + 64;

    auto issue = [&](int kt, int s) {
        int k0 = kt << 5;
        CP_ASYNC16(aBase + ((s * STG + lr  * 40 + lc) << 1), A  + (size_t)(row0 + lr ) * K + k0 + lc);
        CP_ASYNC16(aBase + ((s * STG + lr1 * 40 + lc) << 1), A  + (size_t)(row0 + lr1) * K + k0 + lc);
        CP_ASYNC16(bBase + ((s * STG + lr  * 40 + lc) << 1), Bm + (size_t)(col0 + lr ) * K + k0 + lc);
        CP_ASYNC16(bBase + ((s * STG + lr1 * 40 + lc) << 1), Bm + (size_t)(col0 + lr1) * K + k0 + lc);
        CP_COMMIT();
    };

    issue(0, 0);
    issue(1, 1);
    issue(2, 2);

    for (int kt = 0; kt < NT; kt++) {
        CP_WAIT2();
        __syncthreads();
        if (kt + 3 < NT) issue(kt + 3, (kt + 3) & 3);
        int s = kt & 3;
#pragma unroll
        for (int kk = 0; kk < 32; kk += 16) {
            uint32_t a[4][4], b[4][2];
#pragma unroll
            for (int i = 0; i < 4; i++) {
                int r = m0w + i * 16 + (lane & 15);
                int c = kk + ((lane >> 4) << 3);
                ldsm_x4(a[i][0], a[i][1], a[i][2], a[i][3],
                        aBase + ((s * STG + r * 40 + c) << 1));
            }
#pragma unroll
            for (int j = 0; j < 2; j++) {
                int q = lane >> 3, rr = lane & 7;
                int r = n0w + j * 16 + ((q >> 1) << 3) + rr;
                int c = kk + ((q & 1) << 3);
                uint32_t t0, t1, t2, t3;
                ldsm_x4(t0, t1, t2, t3, bBase + ((s * STG + r * 40 + c) << 1));
                b[2*j][0] = t0; b[2*j][1] = t1; b[2*j+1][0] = t2; b[2*j+1][1] = t3;
            }
#pragma unroll
            for (int i = 0; i < 4; i++)
#pragma unroll
                for (int j = 0; j < 4; j++)
                    mma16816(acc[i][j], a[i][0], a[i][1], a[i][2], a[i][3], b[j][0], b[j][1]);
        }
        __syncthreads();
    }

#pragma unroll
    for (int i = 0; i < 4; i++) {
        int r = row0 + m0w + i * 16 + (lane >> 2);
#pragma unroll
        for (int j = 0; j < 4; j++) {
            int c = col0 + n0w + j * 8 + ((lane & 3) << 1);
            *(float2*)&C[(size_t)r * N + c]       = make_float2(acc[i][j][0], acc[i][j][1]);
            *(float2*)&C[(size_t)(r + 8) * N + c] = make_float2(acc[i][j][2], acc[i][j][3]);
        }
    }
}

// ---------------- fp32 -> fp16 convert ----------------
__global__ void cvt_half(const float* __restrict__ in, __half* __restrict__ out, int n4)
{
    int i = blockIdx.x * blockDim.x + threadIdx.x;
    if (i >= n4) return;
    float4 v = ((const float4*)in)[i];
    union { __half h[4]; uint2 u; } p;
    p.h[0] = __float2half_rn(v.x); p.h[1] = __float2half_rn(v.y);
    p.h[2] = __float2half_rn(v.z); p.h[3] = __float2half_rn(v.w);
    ((uint2*)out)[i] = p.u;
}

__global__ void zero_kernel(float* p, int n)
{
    int i = blockIdx.x * blockDim.x + threadIdx.x;
    if (i < n) p[i] = 0.f;
}

// ---------------- fp32 split-K GEMM for b|a ----------------
__global__ void sgemm_ba(const float* __restrict__ A, const float* __restrict__ Wb,
                         const float* __restrict__ Wa, float* __restrict__ C, int M, int K)
{
    __shared__ float As[16][128];
    __shared__ float Bs[16][64];
    int tid = threadIdx.x;
    int tx = tid & 15, ty = tid >> 4;
    int row0 = blockIdx.y * 128;
    int kBeg = blockIdx.z * (K / 8), kEnd = kBeg + K / 8;

    float acc[8][4];
#pragma unroll
    for (int m = 0; m < 8; m++)
#pragma unroll
        for (int n = 0; n < 4; n++) acc[m][n] = 0.f;

    for (int kt = kBeg; kt < kEnd; kt += 16) {
#pragma unroll
        for (int i = 0; i < 2; i++) {
            int f = tid + i * 256;
            int r = f >> 2, c4 = (f & 3) << 2;
            float4 av = *(const float4*)(A + (size_t)(row0 + r) * K + kt + c4);
            As[c4][r] = av.x; As[c4+1][r] = av.y; As[c4+2][r] = av.z; As[c4+3][r] = av.w;
        }
        {
            int r = tid >> 2, c4 = (tid & 3) << 2;
            if (r < 64) {
                const float* src = (r < 32) ? (Wb + (size_t)r * K) : (Wa + (size_t)(r - 32) * K);
                float4 bv = *(const float4*)(src + kt + c4);
                Bs[c4][r] = bv.x; Bs[c4+1][r] = bv.y; Bs[c4+2][r] = bv.z; Bs[c4+3][r] = bv.w;
            }
        }
        __syncthreads();
#pragma unroll
        for (int k = 0; k < 16; k++) {
            float ra[8], rb[4];
            *(float4*)&ra[0] = *(float4*)&As[k][ty * 8];
            *(float4*)&ra[4] = *(float4*)&As[k][ty * 8 + 4];
            *(float4*)&rb[0] = *(float4*)&Bs[k][tx * 4];
#pragma unroll
            for (int m = 0; m < 8; m++)
#pragma unroll
                for (int n = 0; n < 4; n++) acc[m][n] += ra[m] * rb[n];
        }
        __syncthreads();
    }
#pragma unroll
    for (int m = 0; m < 8; m++) {
        int gr = row0 + ty * 8 + m;
#pragma unroll
        for (int n = 0; n < 4; n++)
            atomicAdd(&C[(size_t)gr * 64 + tx * 4 + n], acc[m][n]);
    }
}

// ---------------- beta / g finalize ----------------
__global__ void betag_kernel(const float* __restrict__ dt_bias, const float* __restrict__ A_log)
{
    int i = blockIdx.x * blockDim.x + threadIdx.x;
    if (i >= BT_ * NV_) return;
    int bt = i >> 5, h = i & 31;
    float braw = g_ba[bt * 64 + h];
    float araw = g_ba[bt * 64 + 32 + h];
    g_beta[i] = 1.f / (1.f + expf(-braw));
    float a = araw + dt_bias[h];
    float sp = (a > 20.f) ? a : log1pf(expf(a));
    g_gg[i] = -expf(A_log[h]) * sp;
}

// ---------------- causal depthwise conv(K=4) + silu, tiled over 8 timesteps ----------------
__global__ __launch_bounds__(256)
void conv_kernel(const float* __restrict__ conv_w,
                 const float* __restrict__ conv_state,
                 const int* __restrict__ input_pos)
{
    int blk = blockIdx.x;
    int b = blk / (T_ / CTT);
    int t0 = (blk % (T_ / CTT)) * CTT;
    int tid = threadIdx.x;
    float keep = (input_pos[0] == 0) ? 0.f : 1.f;

    for (int d = tid; d < CONV_DIM_; d += 256) {
        float4 w = *(const float4*)(conv_w + (size_t)d * 4);
        float xv[CTT + 3];
#pragma unroll
        for (int j = 0; j < CTT + 3; j++) {
            int tt = t0 - 3 + j;
            if (tt >= 0) xv[j] = g_qkv[(size_t)(b * T_ + tt) * CONV_DIM_ + d];
            else         xv[j] = keep * conv_state[((size_t)b * CONV_DIM_ + d) * 4 + (tt + 4)];
        }
#pragma unroll
        for (int to = 0; to < CTT; to++) {
            float acc = w.x * xv[to] + w.y * xv[to+1] + w.z * xv[to+2] + w.w * xv[to+3];
            float s = acc / (1.f + expf(-acc));
            size_t bt = (size_t)(b * T_ + t0 + to);
            if (d < 2048)      g_q[bt * KEY_DIM_ + d] = s;
            else if (d < 4096) g_k[bt * KEY_DIM_ + (d - 2048)] = s;
            else               g_v[bt * VAL_DIM_ + (d - 4096)] = s;
        }
    }
}

// ---------------- q/k L2 normalization ----------------
__global__ __launch_bounds__(256)
void qknorm_kernel()
{
    int gw = blockIdx.x * 8 + (threadIdx.x >> 5);
    int lane = threadIdx.x & 31;
    int bt = gw >> 5, s = gw & 31;
    float* base = (s < 16) ? (g_q + (size_t)bt * KEY_DIM_ + s * 128)
                           : (g_k + (size_t)bt * KEY_DIM_ + (s - 16) * 128);
    float4 v = *(float4*)(base + lane * 4);
    float ss = v.x*v.x + v.y*v.y + v.z*v.z + v.w*v.w;
#pragma unroll
    for (int off = 16; off; off >>= 1) ss += __shfl_xor_sync(0xffffffffu, ss, off);
    float inv = 1.f / fmaxf(sqrtf(ss), 1e-12f);
    v.x *= inv; v.y *= inv; v.z *= inv; v.w *= inv;
    *(float4*)(base + lane * 4) = v;
}

// ---------------- QK precompute (packed f32x2 dot products) ----------------
__global__ __launch_bounds__(256)
void qk_kernel()
{
    extern __shared__ float qsm[];
    float* sq = qsm;
    float* sk = qsm + 64 * 132;

    int bidx = blockIdx.x;
    int ch = bidx % NCH;
    int hk = (bidx / NCH) % NHK_;
    int b  = bidx / (NCH * NHK_);
    int t0 = ch * LCH;
    int tid = threadIdx.x;
    int tx = tid & 15, ty = tid >> 4;

    for (int f = tid; f < 64 * 32; f += 256) {
        int r = f >> 5, c = (f & 31) * 4;
        *(float4*)&sq[r * 132 + c] = *(const float4*)(g_q + (size_t)(b * T_ + t0 + r) * KEY_DIM_ + hk * DK_ + c);
        *(float4*)&sk[r * 132 + c] = *(const float4*)(g_k + (size_t)(b * T_ + t0 + r) * KEY_DIM_ + hk * DK_ + c);
    }
    __syncthreads();

    ull acc2[4][4];
#pragma unroll
    for (int a = 0; a < 4; a++)
#pragma unroll
        for (int c = 0; c < 4; c++) acc2[a][c] = 0ull;

    if (tx * 4 <= ty * 4 + 3) {
        for (int k4 = 0; k4 < DK_; k4 += 4) {
            ull kb0[4], kb1[4];
#pragma unroll
            for (int c = 0; c < 4; c++) {
                kb0[c] = *(ull*)&sk[(tx * 4 + c) * 132 + k4];
                kb1[c] = *(ull*)&sk[(tx * 4 + c) * 132 + k4 + 2];
            }
#pragma unroll
            for (int a = 0; a < 4; a++) {
                ull qa0 = *(ull*)&sq[(ty * 4 + a) * 132 + k4];
                ull qa1 = *(ull*)&sq[(ty * 4 + a) * 132 + k4 + 2];
#pragma unroll
                for (int c = 0; c < 4; c++) {
                    fma2(acc2[a][c], qa0, kb0[c]);
                    fma2(acc2[a][c], qa1, kb1[c]);
                }
            }
        }
    }
    float* dst = g_qk + (size_t)bidx * (LCH * LCH);
#pragma unroll
    for (int a = 0; a < 4; a++) {
        float r[4];
#pragma unroll
        for (int c = 0; c < 4; c++) {
            float2 p = unpack2(acc2[a][c]);
            r[c] = p.x + p.y;
        }
        *(float4*)&dst[(ty * 4 + a) * 64 + tx * 4] = make_float4(r[0], r[1], r[2], r[3]);
    }
}

// ---------------- chunked gated linear-attention recurrence (512 thr, f32x2) ----------------
__global__ __launch_bounds__(512)
void recur_kernel(const float* __restrict__ rstate, const int* __restrict__ input_pos)
{
    extern __shared__ float sm[];
    float* sq = sm;
    float* sk = sq + 64 * 132;
    float* sv = sk + 64 * 132;
    float* sA = sv + 64 * 68;
    float* sS = sA + 64 * 68;
    float* sG = sS + 128 * 68;
    float* sB = sG + 64;
    float* sW = sB + 64;

    int bidx = blockIdx.x;
    int vs = bidx & 1;
    int h  = (bidx >> 1) & (NV_ - 1);
    int b  = bidx >> 6;
    int hk = h >> 1;
    int tid = threadIdx.x;
    int tx = tid & 15, ty = tid >> 4;
    float keep = (input_pos[0] == 0) ? 0.f : 1.f;

#pragma unroll
    for (int j = 0; j < 4; j++) {
        int kk = ty * 4 + j;
        float4 v4 = *(const float4*)(rstate + (((size_t)(b * NV_ + h)) * DK_ + kk) * DV_ + vs * DVS + tx * 4);
        v4.x *= keep; v4.y *= keep; v4.z *= keep; v4.w *= keep;
        *(float4*)&sS[kk * 68 + tx * 4] = v4;
    }

    const float* qkBase = g_qk + ((size_t)(b * NHK_ + hk) * NCH) * (LCH * LCH);

    for (int ch = 0; ch < NCH; ch++) {
        int t0 = ch * LCH;
        __syncthreads();
        for (int f = tid; f < 64 * 32; f += 512) {
            int r = f >> 5, c = (f & 31) * 4;
            *(float4*)&sq[r * 132 + c] = *(const float4*)(g_q + (size_t)(b * T_ + t0 + r) * KEY_DIM_ + hk * DK_ + c);
            *(float4*)&sk[r * 132 + c] = *(const float4*)(g_k + (size_t)(b * T_ + t0 + r) * KEY_DIM_ + hk * DK_ + c);
        }
        for (int f = tid; f < 64 * 16; f += 512) {
            int r = f >> 4, c = (f & 15) * 4;
            *(float4*)&sv[r * 68 + c] = *(const float4*)(g_v + (size_t)(b * T_ + t0 + r) * VAL_DIM_ + h * DV_ + vs * DVS + c);
        }
        if (tid < 64) {
            sB[tid] = g_beta[(b * T_ + t0 + tid) * NV_ + h];
            sG[tid] = g_gg  [(b * T_ + t0 + tid) * NV_ + h];
        }
        __syncthreads();
        if (tid == 0) {
            float run = 0.f;
            for (int i = 0; i < LCH; i++) { run += sG[i]; sG[i] = run; }
        }
        __syncthreads();
        if (tid < 64) {
            float df = sG[63] - sG[tid];
            sW[tid] = (df > -30.f) ? expf(df) * sB[tid] : 0.f;
        }

        // sA[t][i] = QK[t][i] * exp(Gt - Gi) * beta_i, masked i<=t
        {
            const float* qkT = qkBase + (size_t)ch * (LCH * LCH);
            int f0 = tid * 8;
            int t = f0 >> 6, i0 = f0 & 63;
            float gt = sG[t];
            float4 qa = *(const float4*)(qkT + t * 64 + i0);
            float4 qb = *(const float4*)(qkT + t * 64 + i0 + 4);
            float r[8] = {qa.x, qa.y, qa.z, qa.w, qb.x, qb.y, qb.z, qb.w};
#pragma unroll
            for (int j = 0; j < 8; j++) {
                int i = i0 + j;
                float d = gt - sG[i];
                r[j] = (i <= t && d > -30.f) ? r[j] * expf(d) * sB[i] : 0.f;
            }
            *(float4*)&sA[t * 68 + i0]     = make_float4(r[0], r[1], r[2], r[3]);
            *(float4*)&sA[t * 68 + i0 + 4] = make_float4(r[4], r[5], r[6], r[7]);
        }
        __syncthreads();

        int r0 = ty * 2, r1 = r0 + 1;
        ull av2[2][2] = {{0ull,0ull},{0ull,0ull}};
        ull ai2[2][2] = {{0ull,0ull},{0ull,0ull}};
        float gr0 = sG[r0];

        // intra: A @ V with causal break
        for (int i4 = 0; i4 <= r1; i4 += 4) {
            ull vv0[4], vv1[4];
#pragma unroll
            for (int ii = 0; ii < 4; ii++) {
                vv0[ii] = *(ull*)&sv[(i4 + ii) * 68 + tx * 4];
                vv1[ii] = *(ull*)&sv[(i4 + ii) * 68 + tx * 4 + 2];
            }
#pragma unroll
            for (int a = 0; a < 2; a++) {
                float4 avv = *(float4*)&sA[(r0 + a) * 68 + i4];
                ull s;
                s = bcast2(avv.x); fma2(av2[a][0], s, vv0[0]); fma2(av2[a][1], s, vv1[0]);
                s = bcast2(avv.y); fma2(av2[a][0], s, vv0[1]); fma2(av2[a][1], s, vv1[1]);
                s = bcast2(avv.z); fma2(av2[a][0], s, vv0[2]); fma2(av2[a][1], s, vv1[2]);
                s = bcast2(avv.w); fma2(av2[a][0], s, vv0[3]); fma2(av2[a][1], s, vv1[3]);
            }
        }
        // inter: q @ S (skip when exp(G) negligible)
        if (gr0 > -30.f) {
            for (int k4 = 0; k4 < DK_; k4 += 4) {
                ull s0[4], s1[4];
#pragma unroll
                for (int kk = 0; kk < 4; kk++) {
                    s0[kk] = *(ull*)&sS[(k4 + kk) * 68 + tx * 4];
                    s1[kk] = *(ull*)&sS[(k4 + kk) * 68 + tx * 4 + 2];
                }
#pragma unroll
                for (int a = 0; a < 2; a++) {
                    float4 qa = *(float4*)&sq[(r0 + a) * 132 + k4];
                    ull s;
                    s = bcast2(qa.x); fma2(ai2[a][0], s, s0[0]); fma2(ai2[a][1], s, s1[0]);
                    s = bcast2(qa.y); fma2(ai2[a][0], s, s0[1]); fma2(ai2[a][1], s, s1[1]);
                    s = bcast2(qa.z); fma2(ai2[a][0], s, s0[2]); fma2(ai2[a][1], s, s1[2]);
                    s = bcast2(qa.w); fma2(ai2[a][0], s, s0[3]); fma2(ai2[a][1], s, s1[3]);
                }
            }
        }
#pragma unroll
        for (int a = 0; a < 2; a++) {
            int t = r0 + a;
            ull e2 = bcast2(expf(sG[t]));
            fma2(av2[a][0], e2, ai2[a][0]);
            fma2(av2[a][1], e2, ai2[a][1]);
            float* dst = g_o + (size_t)(b * T_ + t0 + t) * VAL_DIM_ + h * DV_ + vs * DVS + tx * 4;
            *(ull*)dst       = av2[a][0];
            *(ull*)(dst + 2) = av2[a][1];
        }
        __syncthreads();

        // S = exp(G_last)*S + sum_i w_i * k_i (outer) v_i
        ull el2 = bcast2(expf(sG[63]));
        ull S0[4], S1[4];
#pragma unroll
        for (int j = 0; j < 4; j++) {
            S0[j] = *(ull*)&sS[(ty * 4 + j) * 68 + tx * 4];
            S1[j] = *(ull*)&sS[(ty * 4 + j) * 68 + tx * 4 + 2];
            mul2(S0[j], el2); mul2(S1[j], el2);
        }
        for (int i = 0; i < LCH; i++) {
            float w = sW[i];
            if (w == 0.f) continue;
            ull v0 = *(ull*)&sv[i * 68 + tx * 4];
            ull v1 = *(ull*)&sv[i * 68 + tx * 4 + 2];
            float4 k0 = *(float4*)&sk[i * 132 + ty * 4];
            ull s;
            s = bcast2(w * k0.x); fma2(S0[0], s, v0); fma2(S1[0], s, v1);
            s = bcast2(w * k0.y); fma2(S0[1], s, v0); fma2(S1[1], s, v1);
            s = bcast2(w * k0.z); fma2(S0[2], s, v0); fma2(S1[2], s, v1);
            s = bcast2(w * k0.w); fma2(S0[3], s, v0); fma2(S1[3], s, v1);
        }
#pragma unroll
        for (int j = 0; j < 4; j++) {
            *(ull*)&sS[(ty * 4 + j) * 68 + tx * 4]     = S0[j];
            *(ull*)&sS[(ty * 4 + j) * 68 + tx * 4 + 2] = S1[j];
        }
    }
}

// ---------------- gated RMSNorm -> fp16 ----------------
__global__ void rmsnorm_kernel(const float* __restrict__ norm_w)
{
    int bh = blockIdx.x;
    int bt = bh >> 5, h = bh & 31;
    int tid = threadIdx.x;
    long idx = (long)bt * VAL_DIM_ + h * DV_ + tid;
    float o = g_o[idx];
    float z = g_z[idx];
    float val = o * (z / (1.f + expf(-z)));
    float s = val * val;
#pragma unroll
    for (int off = 16; off; off >>= 1) s += __shfl_xor_sync(0xffffffffu, s, off);
    __shared__ float red[4];
    int warp = tid >> 5, lane = tid & 31;
    if (lane == 0) red[warp] = s;
    __syncthreads();
    float tot = red[0] + red[1] + red[2] + red[3];
    float scale = rsqrtf(tot * (1.f / 128.f) + 1e-6f) * norm_w[tid];
    g_oh[idx] = __float2half_rn(val * scale);
}

// ---------------- launch (fork-join multi-stream, graph-capturable) ----------------
extern "C" void kernel_launch(void* const* d_in, const int* in_sizes, int n_in,
                              void* d_out, int out_size)
{
    const float* x          = (const float*)d_in[0];
    const int*   input_pos  = (const int*)  d_in[1];
    const float* W_qkv      = (const float*)d_in[2];
    const float* W_z        = (const float*)d_in[3];
    const float* W_b        = (const float*)d_in[4];
    const float* W_a        = (const float*)d_in[5];
    const float* conv_w     = (const float*)d_in[6];
    const float* dt_bias    = (const float*)d_in[7];
    const float* A_log      = (const float*)d_in[8];
    const float* norm_w     = (const float*)d_in[9];
    const float* W_out      = (const float*)d_in[10];
    const float* conv_state = (const float*)d_in[11];
    const float* rstate     = (const float*)d_in[12];
    float* out = (float*)d_out;

    float *p_qkv, *p_z, *p_ba;
    __half *p_xh, *p_Wqh, *p_Wzh, *p_Woh, *p_oh;
    cudaGetSymbolAddress((void**)&p_qkv, g_qkv);
    cudaGetSymbolAddress((void**)&p_z,   g_z);
    cudaGetSymbolAddress((void**)&p_ba,  g_ba);
    cudaGetSymbolAddress((void**)&p_xh,  g_xh);
    cudaGetSymbolAddress((void**)&p_Wqh, g_Wqh);
    cudaGetSymbolAddress((void**)&p_Wzh, g_Wzh);
    cudaGetSymbolAddress((void**)&p_Woh, g_Woh);
    cudaGetSymbolAddress((void**)&p_oh,  g_oh);

    const int RECUR_SMEM = (64*132*2 + 64*68*2 + 128*68 + 64*3) * 4;   // 137984 B
    const int QK_SMEM    = (64*132*2) * 4;                              // 67584 B
    const int HG_SMEM    = 8 * 128 * 40 * 2;                            // 81920 B
    cudaFuncSetAttribute(recur_kernel, cudaFuncAttributeMaxDynamicSharedMemorySize, RECUR_SMEM);
    cudaFuncSetAttribute(qk_kernel,    cudaFuncAttributeMaxDynamicSharedMemorySize, QK_SMEM);
    cudaFuncSetAttribute(hgemm_nt,     cudaFuncAttributeMaxDynamicSharedMemorySize, HG_SMEM);

    static cudaStream_t sZ = nullptr, sBA = nullptr, sWo = nullptr;
    static cudaEvent_t evRoot, evX, evZ, evBA, evWo;
    if (!sZ) {
        cudaStreamCreateWithFlags(&sZ,  cudaStreamNonBlocking);
        cudaStreamCreateWithFlags(&sBA, cudaStreamNonBlocking);
        cudaStreamCreateWithFlags(&sWo, cudaStreamNonBlocking);
        cudaEventCreateWithFlags(&evRoot, cudaEventDisableTiming);
        cudaEventCreateWithFlags(&evX,    cudaEventDisableTiming);
        cudaEventCreateWithFlags(&evZ,    cudaEventDisableTiming);
        cudaEventCreateWithFlags(&evBA,   cudaEventDisableTiming);
        cudaEventCreateWithFlags(&evWo,   cudaEventDisableTiming);
    }

    // ---- fork ----
    cudaEventRecord(evRoot, 0);
    cudaStreamWaitEvent(sZ,  evRoot, 0);
    cudaStreamWaitEvent(sBA, evRoot, 0);
    cudaStreamWaitEvent(sWo, evRoot, 0);

    // main: x cvt -> qkv GEMM -> conv -> qknorm -> qk -> recur -> rmsnorm -> out GEMM
    cvt_half<<<(BT_*C_/4 + 255)/256, 256>>>(x, p_xh, BT_*C_/4);
    cudaEventRecord(evX, 0);
    cvt_half<<<(CONV_DIM_*C_/4 + 255)/256, 256>>>(W_qkv, p_Wqh, CONV_DIM_*C_/4);
    hgemm_nt<<<dim3(CONV_DIM_/128, BT_/128), 256, HG_SMEM>>>(p_xh, p_Wqh, p_qkv, BT_, CONV_DIM_, C_);
    conv_kernel<<<BT_/CTT, 256>>>(conv_w, conv_state, input_pos);
    qknorm_kernel<<<BT_*32/8, 256>>>();
    qk_kernel<<<B_ * NHK_ * NCH, 256, QK_SMEM>>>();

    // z branch
    cvt_half<<<(VAL_DIM_*C_/4 + 255)/256, 256, 0, sZ>>>(W_z, p_Wzh, VAL_DIM_*C_/4);
    cudaStreamWaitEvent(sZ, evX, 0);
    hgemm_nt<<<dim3(VAL_DIM_/128, BT_/128), 256, HG_SMEM, sZ>>>(p_xh, p_Wzh, p_z, BT_, VAL_DIM_, C_);
    cudaEventRecord(evZ, sZ);

    // b/a branch
    zero_kernel<<<(BT_*64 + 255)/256, 256, 0, sBA>>>(p_ba, BT_*64);
    sgemm_ba<<<dim3(1, BT_/128, 8), 256, 0, sBA>>>(x, W_b, W_a, p_ba, BT_, C_);
    betag_kernel<<<(BT_ * NV_ + 255) / 256, 256, 0, sBA>>>(dt_bias, A_log);
    cudaEventRecord(evBA, sBA);

    // Wo branch
    cvt_half<<<(C_*VAL_DIM_/4 + 255)/256, 256, 0, sWo>>>(W_out, p_Woh, C_*VAL_DIM_/4);
    cudaEventRecord(evWo, sWo);

    // join
    cudaStreamWaitEvent(0, evBA, 0);
    recur_kernel<<<B_ * NV_ * SPLITV, 512, RECUR_SMEM>>>(rstate, input_pos);

    cudaStreamWaitEvent(0, evZ, 0);
    rmsnorm_kernel<<<BT_ * NV_, 128>>>(norm_w);

    cudaStreamWaitEvent(0, evWo, 0);
    hgemm_nt<<<dim3(C_/128, BT_/128), 256, HG_SMEM>>>(p_oh, p_Woh, out, BT_, C_, VAL_DIM_);
}